// round 7
// baseline (speedup 1.0000x reference)
#include <cuda_runtime.h>
#include <math.h>

#define NT 128
#define GZ (-9.80665f)

struct SM {
    float A[441], Pn[441], T9[189], L[108];
    float H[24], G[36], GA[42], HP[42], S3[3], r2[2];
    float Rotn[9], Vn[3], Pn3[3], Om[3], vi[3];
    float mir[33];     // Rot 0-8, V 9-11, Pp 12-14, Bom 15-17, Bac 18-20, Rci 21-29, Tci 30-32
    float in[2][9];    // t, u[6], mcov[2]
};

__device__ __forceinline__ float skf(const float* w, int r, int c) {
    if (r == 0) return (c == 0) ? 0.f : ((c == 1) ? -w[2] : w[1]);
    if (r == 1) return (c == 0) ? w[2] : ((c == 1) ? 0.f : -w[0]);
    return (c == 0) ? -w[1] : ((c == 1) ? w[0] : 0.f);
}
__device__ __forceinline__ float skewrowdot(const float* w, const float* R, int rr, int j) {
    if (rr == 0) return -w[2]*R[3+j] + w[1]*R[6+j];
    if (rr == 1) return  w[2]*R[0+j] - w[0]*R[6+j];
    return -w[1]*R[0+j] + w[0]*R[3+j];
}
__device__ __forceinline__ float SG(int rr, int j) {
    if (rr == 0 && j == 1) return -GZ;
    if (rr == 1 && j == 0) return  GZ;
    return 0.f;
}
__device__ __forceinline__ float sgR(const float* R, int rr, int j) {
    if (rr == 0) return -GZ * R[3+j];
    if (rr == 1) return  GZ * R[0+j];
    return 0.f;
}
__device__ __forceinline__ void so3c(float a2, float& c, float& sa, float& oc) {
    c  = 1.f + a2*(-0.5f      + a2*((1.f/24.f)  + a2*(-1.f/720.f)));
    sa = 1.f + a2*((-1.f/6.f) + a2*((1.f/120.f) + a2*(-1.f/5040.f)));
    oc = 0.5f + a2*((-1.f/24.f) + a2*(1.f/720.f));
}
__device__ __forceinline__ float j1c(float a2) {
    return (1.f/6.f) + a2*((-1.f/120.f) + a2*(1.f/5040.f));
}
__device__ __forceinline__ void mm3(const float* A, const float* B, float* C) {
#pragma unroll
    for (int p = 0; p < 3; ++p)
#pragma unroll
        for (int q = 0; q < 3; ++q)
            C[p*3+q] = A[p*3+0]*B[0*3+q] + A[p*3+1]*B[1*3+q] + A[p*3+2]*B[2*3+q];
}
__device__ __forceinline__ void normrot(float* X) {
    for (int it = 0; it < 8; ++it) {
        float Y[9], Z[9];
#pragma unroll
        for (int p = 0; p < 3; ++p)
#pragma unroll
            for (int q = 0; q < 3; ++q)
                Y[p*3+q] = X[p*3+0]*X[q*3+0] + X[p*3+1]*X[q*3+1] + X[p*3+2]*X[q*3+2];
        mm3(Y, X, Z);
#pragma unroll
        for (int m = 0; m < 9; ++m) X[m] = 1.5f*X[m] - 0.5f*Z[m];
    }
}

__global__ void __launch_bounds__(NT, 1)
iekf_kernel(const float* __restrict__ t, const float* __restrict__ u,
            const float* __restrict__ mc, const float* __restrict__ vmes,
            const float* __restrict__ ang0, float* __restrict__ out, int N)
{
    __shared__ SM s;
    const int tid = threadIdx.x;
    const bool isMat = (tid < 96);
    const int ln = tid - 96;

    // ---------- W0-2 decodes: 5 slots/thread ----------
    bool eV[5]; int eII[5], eJJ[5], eJJT[5], eIIB[5], eJJ12[5];
    int eAm[5], eAr[5], eBrx[5]; float eAsc[5], eAqv[5]; bool eT9f[5];
    float Preg[5];
#pragma unroll
    for (int sl = 0; sl < 5; ++sl) {
        int e = tid + sl*96;
        eV[sl] = isMat && (e < 441);
        int ii = 0, jj = 0;
        if (eV[sl]) { ii = e/21; jj = e - ii*21; }
        eII[sl]=ii; eJJ[sl]=jj; eJJT[sl]=jj*21+ii; eIIB[sl]=ii*21; eJJ12[sl]=jj*12;
        eT9f[sl] = (ii < 9);
        int am = 2, ar = 0, brx = 0; float asc = 0.f, aqv = 0.f;
        if (ii<3 && jj<3)                      { am=0; ar=ii*3;     brx=jj*3;     asc=0.001f; }
        else if (ii>=3&&ii<6&&jj>=3&&jj<6)     { am=0; ar=(ii-3)*3; brx=(jj-3)*3; asc=0.01f;  }
        else if (ii==jj) { am=1; aqv=(ii>=9&&ii<12)?6e-9f:(ii>=12&&ii<15)?2e-4f:(ii>=15)?1e-9f:0.f; }
        eAm[sl]=am; eAr[sl]=ar; eBrx[sl]=brx; eAsc[sl]=asc; eAqv[sl]=aqv;
        float pv = 0.f;
        if (ii == jj) {
            if (ii < 2) pv = 0.001f;
            else if (ii >= 3 && ii < 5) pv = 0.1f;
            else if (ii >= 9 && ii < 12) pv = 0.006f;
            else if (ii >= 12 && ii < 15) pv = 0.004f;
            else if (ii >= 15 && ii < 18) pv = 1e-6f;
            else if (ii >= 18) pv = 0.005f;
        }
        Preg[sl] = pv;
    }
    // T9 slots (W0-2)
    const int t9aR12 = (tid/21)*12, t9aC = tid - (tid/21)*21;
    const int t9k2 = tid + 96; const bool t9bV = isMat && (t9k2 < 189);
    int t9bR12 = 0, t9bC = 0;
    if (t9bV) { int r = t9k2/21; t9bR12 = r*12; t9bC = t9k2 - r*21; }
    // L decodes (W0-2)
    int Lbrr = 0, Lrr = 0, Lbc = 0, Lj = 0;
    if (isMat) {
        int r = tid/12, cc = tid - r*12;
        Lbrr = r/3; Lrr = r - Lbrr*3; Lbc = cc/3; Lj = cc - Lbc*3;
    }
    const bool l2V = isMat && (tid < 12);
    const int L2bc = tid/3, L2j = tid - L2bc*3;    // row 8
    // W3 lane decodes
    const int rp = (ln >= 0 && ln < 9) ? ln/3 : 0;
    const int rq = (ln >= 0 && ln < 9) ? ln - rp*3 : 0;
    int ha = 0, hcc = 0, hbb = 0, hj = 0;
    if (ln >= 0 && ln < 24) { ha = ln/12; hcc = ln - ha*12; hbb = hcc/3; hj = hcc - hbb*3; }
    const int ga1A = (ln >= 21) ? 1 : 0;
    const int ga1C = (ln >= 0) ? (ln - ga1A*21) : 0;
    const int svW = (ln >= 9 && ln < 15) ? (ln-9)/3 : 0;
    const int svQ = (ln >= 9 && ln < 15) ? (ln-9) - svW*3 : 0;
    const int rcP = (ln >= 15 && ln < 24) ? (ln-15)/3 : 0;
    const int rcQ = (ln >= 15 && ln < 24) ? (ln-15) - rcP*3 : 0;
    // out pointers (W3)
    float* outP = out; int outStride = 0; float* outP2 = out;
    if (!isMat) {
        int idx = ln;
        if (idx < 9)       { outP = out + idx;             outStride = 9; }
        else if (idx < 12) { outP = out + 9*N  + (idx-9);  outStride = 3; }
        else if (idx < 15) { outP = out + 12*N + (idx-12); outStride = 3; }
        else if (idx < 18) { outP = out + 15*N + (idx-15); outStride = 3; }
        else if (idx < 21) { outP = out + 18*N + (idx-18); outStride = 3; }
        else if (idx < 30) { outP = out + 21*N + (idx-21); outStride = 9; }
        else               { outP = out + 30*N + (idx-30); outStride = 3; }
        outP2 = out + 30*N + 2;   // mir[32], lane 0 only
    }
    // prefetch pointers (W3 lanes 0..8)
    const float* pfP = t; int pfStride = 0;
    if (!isMat && ln < 9) {
        if (ln == 0)     { pfP = t  + 2;           pfStride = 1; }
        else if (ln < 7) { pfP = u  + 12 + (ln-1); pfStride = 6; }
        else             { pfP = mc + 4  + (ln-7); pfStride = 2; }
    }

    // ---------- prologue ----------
    float tprev = t[0];
    if (tid < 9) {
        float v;
        if (tid == 0) v = t[1];
        else if (tid < 7) v = u[6 + (tid-1)];
        else v = mc[2 + (tid-7)];
        s.in[1][tid] = v;
    }
    if (tid == 96) {
        float a0 = ang0[0], a1 = ang0[1], a2 = ang0[2];
        float cr = cosf(a0), sr = sinf(a0), cp = cosf(a1), sp = sinf(a1);
        float cy = cosf(a2), sy = sinf(a2);
        float Rx[9] = {1,0,0, 0,cr,-sr, 0,sr,cr};
        float Ry[9] = {cp,0,sp, 0,1,0, -sp,0,cp};
        float Rz[9] = {cy,-sy,0, sy,cy,0, 0,0,1};
        float T[9], R0[9];
        mm3(Rz, Ry, T); mm3(T, Rx, R0);
#pragma unroll
        for (int m = 0; m < 9; ++m) { s.mir[m] = R0[m]; s.mir[21+m] = (m==0||m==4||m==8) ? 1.f : 0.f; }
#pragma unroll
        for (int q = 0; q < 3; ++q) {
            s.mir[9+q] = vmes[q]; s.mir[12+q] = 0.f; s.mir[15+q] = 0.f;
            s.mir[18+q] = 0.f; s.mir[30+q] = 0.f;
        }
    }
    __syncthreads();

    // ---------- main loop ----------
    for (int i = 1; i < N; ++i) {
        const int cur = i & 1;
        const float tcv = s.in[cur][0];
        const float dt = tcv - tprev; tprev = tcv;
        const float dt2 = dt*dt;

        // ======== PHASE 1 ========
        float pf = 0.f;
        if (isMat) {
            const float dt3 = dt2*dt;
            // A from register P
#pragma unroll
            for (int sl = 0; sl < 5; ++sl) if (eV[sl]) {
                int e = tid + sl*96;
                float gq = 0.f;
                if (eAm[sl] == 0) {
                    float d = s.mir[eAr[sl]]*s.mir[eBrx[sl]] + s.mir[eAr[sl]+1]*s.mir[eBrx[sl]+1]
                            + s.mir[eAr[sl]+2]*s.mir[eBrx[sl]+2];
                    gq = eAsc[sl] * dt2 * d;
                } else if (eAm[sl] == 1) gq = eAqv[sl] * dt2;
                s.A[e] = Preg[sl] + gq;
            }
            // L
            {
                const float* Rm = s.mir; const float* Vm = s.mir + 9; const float* Pm = s.mir + 12;
                float v = 0.f;
                if (Lbrr == 0) {
                    if (Lbc == 2) v = -dt * Rm[Lrr*3+Lj];
                } else if (Lbrr == 1) {
                    if (Lbc == 0)      v = dt * SG(Lrr, Lj);
                    else if (Lbc == 2) v = -dt*skewrowdot(Vm, Rm, Lrr, Lj) - 0.5f*dt2*sgR(Rm, Lrr, Lj);
                    else if (Lbc == 3) v = -dt * Rm[Lrr*3+Lj];
                } else {
                    if (Lbc == 0)      v = 0.5f*dt2*SG(Lrr, Lj);
                    else if (Lbc == 1) v = (Lrr == Lj) ? dt : 0.f;
                    else if (Lbc == 2) v = -dt*skewrowdot(Pm, Rm, Lrr, Lj)
                                           - 0.5f*dt2*skewrowdot(Vm, Rm, Lrr, Lj)
                                           - (dt3*(1.f/6.f))*sgR(Rm, Lrr, Lj);
                    else               v = -0.5f*dt2*Rm[Lrr*3+Lj];
                }
                s.L[tid] = v;
                if (l2V) {
                    float v2 = 0.f;
                    if (L2bc == 0)      v2 = 0.5f*dt2*SG(2, L2j);
                    else if (L2bc == 1) v2 = (2 == L2j) ? dt : 0.f;
                    else if (L2bc == 2) v2 = -dt*skewrowdot(Pm, Rm, 2, L2j)
                                             - 0.5f*dt2*skewrowdot(Vm, Rm, 2, L2j)
                                             - (dt3*(1.f/6.f))*sgR(Rm, 2, L2j);
                    else                v2 = -0.5f*dt2*Rm[6+L2j];
                    s.L[96+tid] = v2;
                }
            }
        } else {
            // W3: outputs, prefetch, measurement chain
            *outP = s.mir[ln]; outP += outStride;
            if (ln == 0) { *outP2 = s.mir[32]; outP2 += 3; }
            if (ln < 9 && (i + 1 < N)) { pf = *pfP; pfP += pfStride; }
            const float gy0 = s.in[cur][1], gy1 = s.in[cur][2], gy2 = s.in[cur][3];
            const float ac0 = s.in[cur][4], ac1 = s.in[cur][5], ac2 = s.in[cur][6];
            if (ln < 9) {
                float ph[3] = {(gy0 - s.mir[15])*dt, (gy1 - s.mir[16])*dt, (gy2 - s.mir[17])*dt};
                float a2 = ph[0]*ph[0] + ph[1]*ph[1] + ph[2]*ph[2];
                float c, sa, oc; so3c(a2, c, sa, oc);
                float e0 = ((0==rq)?c:0.f) + oc*ph[0]*ph[rq] + sa*skf(ph, 0, rq);
                float e1 = ((1==rq)?c:0.f) + oc*ph[1]*ph[rq] + sa*skf(ph, 1, rq);
                float e2 = ((2==rq)?c:0.f) + oc*ph[2]*ph[rq] + sa*skf(ph, 2, rq);
                s.Rotn[ln] = s.mir[rp*3+0]*e0 + s.mir[rp*3+1]*e1 + s.mir[rp*3+2]*e2;
            } else if (ln < 15) {
                float d0 = ac0 - s.mir[18], d1 = ac1 - s.mir[19], d2 = ac2 - s.mir[20];
                float accq = s.mir[svQ*3+0]*d0 + s.mir[svQ*3+1]*d1 + s.mir[svQ*3+2]*d2 + ((svQ==2)?GZ:0.f);
                if (svW == 0) s.Vn[svQ]  = s.mir[9+svQ] + accq*dt;
                else          s.Pn3[svQ] = s.mir[12+svQ] + s.mir[9+svQ]*dt + 0.5f*accq*dt2;
            } else if (ln < 18) {
                int q = ln - 15;
                s.Om[q] = ((q==0)?gy0:(q==1)?gy1:gy2) - s.mir[15+q];
            }
            __syncwarp();
            if (ln >= 18 && ln < 21) {
                int q = ln - 18;
                s.vi[q] = s.Rotn[q]*s.Vn[0] + s.Rotn[3+q]*s.Vn[1] + s.Rotn[6+q]*s.Vn[2];
            }
            __syncwarp();
            if (ln < 24) {
                float hv;
                if (hbb == 0) {
                    hv = s.Rotn[hj*3+0]*s.mir[21+ha+1] + s.Rotn[hj*3+1]*s.mir[24+ha+1] + s.Rotn[hj*3+2]*s.mir[27+ha+1];
                } else if (hbb == 1) {
                    hv = skf(s.mir+30, ha+1, hj);
                } else if (hbb == 2) {
                    hv = s.mir[21+ha+1]*skf(s.vi,0,hj) + s.mir[24+ha+1]*skf(s.vi,1,hj) + s.mir[27+ha+1]*skf(s.vi,2,hj);
                } else {
                    hv = -skf(s.Om, ha+1, hj);
                }
                s.H[ha*12+hcc] = hv;
            } else if (ln < 26) {
                int a = ln - 24;
                float cxa = (a==0) ? (s.mir[32]*s.Om[0] - s.mir[30]*s.Om[2])
                                   : (s.mir[30]*s.Om[1] - s.mir[31]*s.Om[0]);
                float vb = s.mir[21+a+1]*s.vi[0] + s.mir[24+a+1]*s.vi[1] + s.mir[27+a+1]*s.vi[2] + cxa;
                s.r2[a] = -vb;
            }
            __syncwarp();
            if (ln < 18) {
                int m = ln;
                float g0, g1;
                if (m == 0)      { float f = dt*GZ;  g0 = s.H[1]*f;  g1 = s.H[13]*f; }
                else if (m == 1) { float f = -dt*GZ; g0 = s.H[0]*f;  g1 = s.H[12]*f; }
                else if (m == 2) { g0 = 0.f; g1 = 0.f; }
                else if (m < 6)  { g0 = s.H[m-3]; g1 = s.H[12+m-3]; }
                else if (m < 9) {
                    int j = m - 6;
                    float l0 = -dt*skewrowdot(s.mir+9, s.mir, 0, j) - 0.5f*dt2*sgR(s.mir, 0, j);
                    float l1 = -dt*skewrowdot(s.mir+9, s.mir, 1, j) - 0.5f*dt2*sgR(s.mir, 1, j);
                    float l2 = -dt*skewrowdot(s.mir+9, s.mir, 2, j) - 0.5f*dt2*sgR(s.mir, 2, j);
                    g0 = s.H[3+j]  + s.H[0]*l0  + s.H[1]*l1  + s.H[2]*l2;
                    g1 = s.H[15+j] + s.H[12]*l0 + s.H[13]*l1 + s.H[14]*l2;
                } else if (m < 12) {
                    int j = m - 9;
                    float l0 = -dt*s.mir[j], l1 = -dt*s.mir[3+j], l2 = -dt*s.mir[6+j];
                    g0 = s.H[0]*l0  + s.H[1]*l1  + s.H[2]*l2;
                    g1 = s.H[12]*l0 + s.H[13]*l1 + s.H[14]*l2;
                } else { g0 = s.H[m-6]; g1 = s.H[12+m-6]; }
                s.G[m] = g0; s.G[18+m] = g1;
            }
        }
        __syncthreads();

        // ======== PHASE 2: W0-2 T9 ; W3 GA -> HP, S ========
        if (isMat) {
            float a = s.A[tid];
#pragma unroll
            for (int m = 0; m < 12; ++m) {
                int col = (m < 6) ? m : m + 3;
                a += s.L[t9aR12+m] * s.A[col*21 + t9aC];
            }
            s.T9[tid] = a;
            if (t9bV) {
                float b = s.A[t9k2];
#pragma unroll
                for (int m = 0; m < 12; ++m) {
                    int col = (m < 6) ? m : m + 3;
                    b += s.L[t9bR12+m] * s.A[col*21 + t9bC];
                }
                s.T9[t9k2] = b;
            }
        } else {
            {
                float acc = 0.f;
#pragma unroll
                for (int m = 0; m < 18; ++m) {
                    int col = (m < 6) ? m : m + 3;
                    acc += s.G[ga1A*18+m] * s.A[col*21 + ga1C];
                }
                s.GA[ln] = acc;
                if (ln < 10) {
                    int c2i = ln + 11;
                    float acc2 = 0.f;
#pragma unroll
                    for (int m = 0; m < 18; ++m) {
                        int col = (m < 6) ? m : m + 3;
                        acc2 += s.G[18+m] * s.A[col*21 + c2i];
                    }
                    s.GA[32+ln] = acc2;
                }
            }
            __syncwarp();
            {
                float hp = s.GA[ln];
                if (ga1C < 9) {
#pragma unroll
                    for (int m = 0; m < 12; ++m) {
                        int col = (m < 6) ? m : m + 3;
                        hp += s.GA[ga1A*21+col] * s.L[ga1C*12+m];
                    }
                }
                s.HP[ln] = hp;
                if (ln < 10) s.HP[32+ln] = s.GA[32+ln];
                if (ln >= 29) {
                    int m = ln - 29;
                    int a = (m == 2) ? 1 : 0;
                    int bb = (m == 0) ? 0 : 1;
                    float acc = 0.f;
#pragma unroll
                    for (int mm = 0; mm < 18; ++mm) {
                        int col = (mm < 6) ? mm : mm + 3;
                        acc += s.GA[a*21+col] * s.G[bb*18+mm];
                    }
                    if (a == bb) acc += s.in[cur][7+a];
                    s.S3[m] = acc;
                }
            }
        }
        __syncthreads();

        // ======== PHASE 3: W0-2 Pn ========
        if (isMat) {
#pragma unroll
            for (int sl = 0; sl < 5; ++sl) if (eV[sl]) {
                int e = tid + sl*96;
                float b = eT9f[sl] ? s.T9[e] : s.A[e];
                if (eJJ[sl] < 9) {
#pragma unroll
                    for (int m = 0; m < 12; ++m) {
                        int col = (m < 6) ? m : m + 3;
                        float brc = eT9f[sl] ? s.T9[eIIB[sl]+col] : s.A[eIIB[sl]+col];
                        b += brc * s.L[eJJ12[sl]+m];
                    }
                }
                s.Pn[e] = b;
            }
        }
        __syncthreads();

        // ======== PHASE 4: W0-2 Joseph -> Preg ; W3 state update ========
        if (isMat) {
            const float S00 = s.S3[0], S01 = s.S3[1], S11 = s.S3[2];
            const float idet = 1.f / (S00*S11 - S01*S01);
            const float Si00 = S11*idet, Si01 = -S01*idet, Si11 = S00*idet;
#pragma unroll
            for (int sl = 0; sl < 5; ++sl) if (eV[sl]) {
                int e = tid + sl*96;
                float hp0i = s.HP[eII[sl]], hp1i = s.HP[21+eII[sl]];
                float hp0j = s.HP[eJJ[sl]], hp1j = s.HP[21+eJJ[sl]];
                float Ki0 = Si00*hp0i + Si01*hp1i, Ki1 = Si01*hp0i + Si11*hp1i;
                float Kj0 = Si00*hp0j + Si01*hp1j, Kj1 = Si01*hp0j + Si11*hp1j;
                float KSi0 = Ki0*S00 + Ki1*S01, KSi1 = Ki0*S01 + Ki1*S11;
                Preg[sl] = 0.5f*(s.Pn[e] + s.Pn[eJJT[sl]])
                         - (Ki0*hp0j + Ki1*hp1j) - (Kj0*hp0i + Kj1*hp1i)
                         + (KSi0*Kj0 + KSi1*Kj1);
            }
        } else {
            const float S00 = s.S3[0], S01 = s.S3[1], S11 = s.S3[2];
            const float idet = 1.f / (S00*S11 - S01*S01);
            const float Si00 = S11*idet, Si01 = -S01*idet, Si11 = S00*idet;
            const float r0 = s.r2[0], r1 = s.r2[1];
            const float w0 = Si00*r0 + Si01*r1, w1 = Si01*r0 + Si11*r1;
#define DX(c) (s.HP[(c)]*w0 + s.HP[21+(c)]*w1)
            float sv = 0.f, tciu = 0.f;
            if (ln < 9) {
                float xi[3] = {DX(0), DX(1), DX(2)};
                float a2 = xi[0]*xi[0] + xi[1]*xi[1] + xi[2]*xi[2];
                float c, sa, oc; so3c(a2, c, sa, oc);
                float d0 = ((rp==0)?c:0.f) + oc*xi[rp]*xi[0] + sa*skf(xi, rp, 0);
                float d1 = ((rp==1)?c:0.f) + oc*xi[rp]*xi[1] + sa*skf(xi, rp, 1);
                float d2 = ((rp==2)?c:0.f) + oc*xi[rp]*xi[2] + sa*skf(xi, rp, 2);
                sv = d0*s.Rotn[rq] + d1*s.Rotn[3+rq] + d2*s.Rotn[6+rq];
            } else if (ln < 15) {
                float xi[3] = {DX(0), DX(1), DX(2)};
                float a2 = xi[0]*xi[0] + xi[1]*xi[1] + xi[2]*xi[2];
                float c, sa, oc; so3c(a2, c, sa, oc);
                float j1 = j1c(a2);
                float y0 = svW ? DX(6) : DX(3);
                float y1 = svW ? DX(7) : DX(4);
                float y2 = svW ? DX(8) : DX(5);
                float J0 = ((svQ==0)?sa:0.f) + j1*xi[svQ]*xi[0] + oc*skf(xi, svQ, 0);
                float J1 = ((svQ==1)?sa:0.f) + j1*xi[svQ]*xi[1] + oc*skf(xi, svQ, 1);
                float J2 = ((svQ==2)?sa:0.f) + j1*xi[svQ]*xi[2] + oc*skf(xi, svQ, 2);
                float x = J0*y0 + J1*y1 + J2*y2;
                float d0 = ((svQ==0)?c:0.f) + oc*xi[svQ]*xi[0] + sa*skf(xi, svQ, 0);
                float d1 = ((svQ==1)?c:0.f) + oc*xi[svQ]*xi[1] + sa*skf(xi, svQ, 1);
                float d2 = ((svQ==2)?c:0.f) + oc*xi[svQ]*xi[2] + sa*skf(xi, svQ, 2);
                const float* src = svW ? s.Pn3 : s.Vn;
                sv = d0*src[0] + d1*src[1] + d2*src[2] + x;
            } else if (ln < 24) {
                float yi[3] = {DX(15), DX(16), DX(17)};
                float a2 = yi[0]*yi[0] + yi[1]*yi[1] + yi[2]*yi[2];
                float c, sa, oc; so3c(a2, c, sa, oc);
                float e0 = ((rcP==0)?c:0.f) + oc*yi[rcP]*yi[0] + sa*skf(yi, rcP, 0);
                float e1 = ((rcP==1)?c:0.f) + oc*yi[rcP]*yi[1] + sa*skf(yi, rcP, 1);
                float e2 = ((rcP==2)?c:0.f) + oc*yi[rcP]*yi[2] + sa*skf(yi, rcP, 2);
                sv = e0*s.mir[21+rcQ] + e1*s.mir[24+rcQ] + e2*s.mir[27+rcQ];
            } else if (ln < 27) {
                int q = ln - 24;
                sv   = s.mir[15+q] + DX(9+q);
                tciu = s.mir[30+q] + DX(18+q);
            } else if (ln < 30) {
                int q = ln - 27;
                sv = s.mir[18+q] + DX(12+q);
            }
#undef DX
            __syncwarp();
            if (ln < 15)       s.mir[ln] = sv;
            else if (ln < 24)  s.mir[21+(ln-15)] = sv;
            else if (ln < 27)  { s.mir[15+(ln-24)] = sv; s.mir[30+(ln-24)] = tciu; }
            else if (ln < 30)  s.mir[18+(ln-27)] = sv;
            if (ln < 9 && (i + 1 < N)) s.in[cur^1][ln] = pf;
            __syncwarp();
            if (i % 100 == 0) {
                if (ln == 0) {
                    float X[9];
#pragma unroll
                    for (int m = 0; m < 9; ++m) X[m] = s.mir[m];
                    normrot(X);
#pragma unroll
                    for (int m = 0; m < 9; ++m) s.mir[m] = X[m];
                }
                if ((i % 1000 == 0) && ln == 1) {
                    float X[9];
#pragma unroll
                    for (int m = 0; m < 9; ++m) X[m] = s.mir[21+m];
                    normrot(X);
#pragma unroll
                    for (int m = 0; m < 9; ++m) s.mir[21+m] = X[m];
                }
            }
        }
        __syncthreads();
    }

    // ---------- epilogue: final state row (W3) ----------
    if (!isMat) {
        *outP = s.mir[ln];
        if (ln == 0) *outP2 = s.mir[32];
    }
}

extern "C" void kernel_launch(void* const* d_in, const int* in_sizes, int n_in,
                              void* d_out, int out_size) {
    const float* t    = (const float*)d_in[0];
    const float* u    = (const float*)d_in[1];
    const float* mcov = (const float*)d_in[2];
    const float* vmes = (const float*)d_in[3];
    const float* ang0 = (const float*)d_in[5];
    float* out = (float*)d_out;
    int N = in_sizes[0];
    iekf_kernel<<<1, NT>>>(t, u, mcov, vmes, ang0, out, N);
}

// round 9
// speedup vs baseline: 1.5924x; 1.5924x over previous
#include <cuda_runtime.h>
#include <math.h>

#define NT 128
#define GZ (-9.80665f)

struct SM {
    float A[441], Pn[441], T9[189], L[108];
    float G[36], GA[42], HP[42], S3[3];
    float mir[33];     // Rot 0-8, V 9-11, Pp 12-14, Bom 15-17, Bac 18-20, Rci 21-29, Tci 30-32
    float in[2][9];    // t, u[6], mcov[2]
};

__device__ __forceinline__ float skf(const float* w, int r, int c) {
    if (r == 0) return (c == 0) ? 0.f : ((c == 1) ? -w[2] : w[1]);
    if (r == 1) return (c == 0) ? w[2] : ((c == 1) ? 0.f : -w[0]);
    return (c == 0) ? -w[1] : ((c == 1) ? w[0] : 0.f);
}
__device__ __forceinline__ float skewrowdot(const float* w, const float* R, int rr, int j) {
    if (rr == 0) return -w[2]*R[3+j] + w[1]*R[6+j];
    if (rr == 1) return  w[2]*R[0+j] - w[0]*R[6+j];
    return -w[1]*R[0+j] + w[0]*R[3+j];
}
__device__ __forceinline__ float SG(int rr, int j) {
    if (rr == 0 && j == 1) return -GZ;
    if (rr == 1 && j == 0) return  GZ;
    return 0.f;
}
__device__ __forceinline__ float sgR(const float* R, int rr, int j) {
    if (rr == 0) return -GZ * R[3+j];
    if (rr == 1) return  GZ * R[0+j];
    return 0.f;
}
__device__ __forceinline__ void so3c(float a2, float& c, float& sa, float& oc) {
    c  = 1.f + a2*(-0.5f      + a2*((1.f/24.f)  + a2*(-1.f/720.f)));
    sa = 1.f + a2*((-1.f/6.f) + a2*((1.f/120.f) + a2*(-1.f/5040.f)));
    oc = 0.5f + a2*((-1.f/24.f) + a2*(1.f/720.f));
}
__device__ __forceinline__ float j1c(float a2) {
    return (1.f/6.f) + a2*((-1.f/120.f) + a2*(1.f/5040.f));
}
__device__ __forceinline__ void mm3(const float* A, const float* B, float* C) {
#pragma unroll
    for (int p = 0; p < 3; ++p)
#pragma unroll
        for (int q = 0; q < 3; ++q)
            C[p*3+q] = A[p*3+0]*B[0*3+q] + A[p*3+1]*B[1*3+q] + A[p*3+2]*B[2*3+q];
}
__device__ __forceinline__ void normrot(float* X) {
    for (int it = 0; it < 8; ++it) {
        float Y[9], Z[9];
#pragma unroll
        for (int p = 0; p < 3; ++p)
#pragma unroll
            for (int q = 0; q < 3; ++q)
                Y[p*3+q] = X[p*3+0]*X[q*3+0] + X[p*3+1]*X[q*3+1] + X[p*3+2]*X[q*3+2];
        mm3(Y, X, Z);
#pragma unroll
        for (int m = 0; m < 9; ++m) X[m] = 1.5f*X[m] - 0.5f*Z[m];
    }
}

__global__ void __launch_bounds__(NT, 1)
iekf_kernel(const float* __restrict__ t, const float* __restrict__ u,
            const float* __restrict__ mc, const float* __restrict__ vmes,
            const float* __restrict__ ang0, float* __restrict__ out, int N)
{
    __shared__ SM s;
    const int tid = threadIdx.x;
    const bool isMat = (tid < 96);

    // ---------- matrix decodes: 5 slots/thread over 96 threads ----------
    bool eV[5]; int eII[5], eJJ[5], eJJT[5], eIIB[5], eJJ12[5];
    int eAm[5], eAr[5], eBrx[5]; float eAsc[5], eAqv[5]; bool eT9f[5];
#pragma unroll
    for (int sl = 0; sl < 5; ++sl) {
        int e = tid + sl*96;
        eV[sl] = isMat && (e < 441);
        int ii = 0, jj = 0;
        if (eV[sl]) { ii = e/21; jj = e - ii*21; }
        eII[sl]=ii; eJJ[sl]=jj; eJJT[sl]=jj*21+ii; eIIB[sl]=ii*21; eJJ12[sl]=jj*12;
        eT9f[sl] = (ii < 9);
        int am = 2, ar = 0, brx = 0; float asc = 0.f, aqv = 0.f;
        if (ii<3 && jj<3)                      { am=0; ar=ii*3;     brx=jj*3;     asc=0.001f; }
        else if (ii>=3&&ii<6&&jj>=3&&jj<6)     { am=0; ar=(ii-3)*3; brx=(jj-3)*3; asc=0.01f;  }
        else if (ii==jj) { am=1; aqv=(ii>=9&&ii<12)?6e-9f:(ii>=12&&ii<15)?2e-4f:(ii>=15)?1e-9f:0.f; }
        eAm[sl]=am; eAr[sl]=ar; eBrx[sl]=brx; eAsc[sl]=asc; eAqv[sl]=aqv;
    }
    // T9 slots (tid<96: elem tid; tid<93: elem tid+96)
    const int t9aR12 = (tid/21)*12, t9aC = tid - (tid/21)*21;
    const int t9k2 = tid + 96; const bool t9bV = isMat && (t9k2 < 189);
    int t9bR12 = 0, t9bC = 0;
    if (t9bV) { int r = t9k2/21; t9bR12 = r*12; t9bC = t9k2 - r*21; }
    // L decodes (tid<96 primary; tid<12 secondary = row 8)
    int Lbrr = 0, Lrr = 0, Lbc = 0, Lj = 0;
    if (isMat) {
        int r = tid/12, cc = tid - r*12;
        Lbrr = r/3; Lrr = r - Lbrr*3; Lbc = cc/3; Lj = cc - Lbc*3;
    }
    const bool l2V = isMat && (tid < 12);
    const int L2bc = tid/3, L2j = tid - L2bc*3;
    // GA (tid 64..105)
    const bool gaV = (tid >= 64 && tid < 106);
    int gaA = 0, gaC = 0;
    if (gaV) { int k = tid - 64; gaA = k/21; gaC = k - gaA*21; }
    // HP (tid 86..127)
    const bool hpV = (tid >= 86);
    int hpA = 0, hpC = 0;
    if (hpV) { int k = tid - 86; hpA = k/21; hpC = k - hpA*21; }
    // out pointers (tid<33)
    float* outP = out; int outStride = 0;
    if (tid < 9)       { outP = out + tid;              outStride = 9; }
    else if (tid < 12) { outP = out + 9*N  + (tid-9);   outStride = 3; }
    else if (tid < 15) { outP = out + 12*N + (tid-12);  outStride = 3; }
    else if (tid < 18) { outP = out + 15*N + (tid-15);  outStride = 3; }
    else if (tid < 21) { outP = out + 18*N + (tid-18);  outStride = 3; }
    else if (tid < 30) { outP = out + 21*N + (tid-21);  outStride = 9; }
    else if (tid < 33) { outP = out + 30*N + (tid-30);  outStride = 3; }
    // prefetch pointers (tid 64..72)
    const float* pfP = t; int pfStride = 0;
    const bool pfV = (tid >= 64 && tid < 73);
    if (pfV) {
        int q = tid - 64;
        if (q == 0)      { pfP = t  + 2;           pfStride = 1; }
        else if (q < 7)  { pfP = u  + 12 + (q-1);  pfStride = 6; }
        else             { pfP = mc + 4  + (q-7);  pfStride = 2; }
    }

    // chain-lane persistent registers (tid 96)
    float Rg[9], Vg[3], Ppg[3], Bomg[3], Bacg[3], Rcig[9], Tcig[3];
    float rn[9], vn[3], pn3[3], omg[3], vig[3], r2g[2];

    // ---------- prologue ----------
    float tprev = t[0];
    // Pn = P0, HP = 0, S3 = I  so first fused Joseph yields P0
#pragma unroll
    for (int sl = 0; sl < 5; ++sl) if (eV[sl]) {
        int e = tid + sl*96;
        int ii = eII[sl], jj = eJJ[sl];
        float pv = 0.f;
        if (ii == jj) {
            if (ii < 2) pv = 0.001f;
            else if (ii >= 3 && ii < 5) pv = 0.1f;
            else if (ii >= 9 && ii < 12) pv = 0.006f;
            else if (ii >= 12 && ii < 15) pv = 0.004f;
            else if (ii >= 15 && ii < 18) pv = 1e-6f;
            else if (ii >= 18) pv = 0.005f;
        }
        s.Pn[e] = pv;
    }
    if (tid < 42) s.HP[tid] = 0.f;
    if (tid == 42) { s.S3[0] = 1.f; s.S3[1] = 0.f; s.S3[2] = 1.f; }
    if (tid < 9) {
        float v;
        if (tid == 0) v = t[1];
        else if (tid < 7) v = u[6 + (tid-1)];
        else v = mc[2 + (tid-7)];
        s.in[1][tid] = v;
    }
    if (tid == 96) {
        float a0 = ang0[0], a1 = ang0[1], a2 = ang0[2];
        float cr = cosf(a0), sr = sinf(a0), cp = cosf(a1), sp = sinf(a1);
        float cy = cosf(a2), sy = sinf(a2);
        float Rx[9] = {1,0,0, 0,cr,-sr, 0,sr,cr};
        float Ry[9] = {cp,0,sp, 0,1,0, -sp,0,cp};
        float Rz[9] = {cy,-sy,0, sy,cy,0, 0,0,1};
        float T[9];
        mm3(Rz, Ry, T); mm3(T, Rx, Rg);
#pragma unroll
        for (int m = 0; m < 9; ++m) Rcig[m] = (m==0||m==4||m==8) ? 1.f : 0.f;
#pragma unroll
        for (int q = 0; q < 3; ++q) {
            Vg[q] = vmes[q]; Ppg[q] = 0.f; Bomg[q] = 0.f; Bacg[q] = 0.f; Tcig[q] = 0.f;
        }
#pragma unroll
        for (int m = 0; m < 9; ++m) s.mir[m] = Rg[m];
#pragma unroll
        for (int q = 0; q < 3; ++q) {
            s.mir[9+q] = Vg[q]; s.mir[12+q] = Ppg[q]; s.mir[15+q] = Bomg[q];
            s.mir[18+q] = Bacg[q]; s.mir[30+q] = Tcig[q];
        }
#pragma unroll
        for (int m = 0; m < 9; ++m) s.mir[21+m] = Rcig[m];
    }
    __syncthreads();

    // ---------- main loop ----------
    for (int i = 1; i < N; ++i) {
        const int cur = i & 1;
        const float tcv = s.in[cur][0];
        const float dt = tcv - tprev; tprev = tcv;
        const float dt2 = dt*dt;

        // ======== PHASE 1: matrix A=Joseph+gq, L ; out ; prefetch ; chain ========
        float pf = 0.f;
        if (isMat) {
            const float dt3 = dt2*dt;
            const float S00 = s.S3[0], S01 = s.S3[1], S11 = s.S3[2];
            const float idet = 1.f / (S00*S11 - S01*S01);
            const float Si00 = S11*idet, Si01 = -S01*idet, Si11 = S00*idet;
#pragma unroll
            for (int sl = 0; sl < 5; ++sl) if (eV[sl]) {
                int e = tid + sl*96;
                // Joseph of previous step
                float hp0i = s.HP[eII[sl]], hp1i = s.HP[21+eII[sl]];
                float hp0j = s.HP[eJJ[sl]], hp1j = s.HP[21+eJJ[sl]];
                float Ki0 = Si00*hp0i + Si01*hp1i, Ki1 = Si01*hp0i + Si11*hp1i;
                float Kj0 = Si00*hp0j + Si01*hp1j, Kj1 = Si01*hp0j + Si11*hp1j;
                float KSi0 = Ki0*S00 + Ki1*S01, KSi1 = Ki0*S01 + Ki1*S11;
                float pj = 0.5f*(s.Pn[e] + s.Pn[eJJT[sl]])
                         - (Ki0*hp0j + Ki1*hp1j) - (Kj0*hp0i + Kj1*hp1i)
                         + (KSi0*Kj0 + KSi1*Kj1);
                // plus GQG^T for this step
                float gq = 0.f;
                if (eAm[sl] == 0) {
                    float d = s.mir[eAr[sl]]*s.mir[eBrx[sl]] + s.mir[eAr[sl]+1]*s.mir[eBrx[sl]+1]
                            + s.mir[eAr[sl]+2]*s.mir[eBrx[sl]+2];
                    gq = eAsc[sl] * dt2 * d;
                } else if (eAm[sl] == 1) gq = eAqv[sl] * dt2;
                s.A[e] = pj + gq;
            }
            // L
            {
                const float* Rm = s.mir; const float* Vm = s.mir + 9; const float* Pm = s.mir + 12;
                float v = 0.f;
                if (Lbrr == 0) {
                    if (Lbc == 2) v = -dt * Rm[Lrr*3+Lj];
                } else if (Lbrr == 1) {
                    if (Lbc == 0)      v = dt * SG(Lrr, Lj);
                    else if (Lbc == 2) v = -dt*skewrowdot(Vm, Rm, Lrr, Lj) - 0.5f*dt2*sgR(Rm, Lrr, Lj);
                    else if (Lbc == 3) v = -dt * Rm[Lrr*3+Lj];
                } else {
                    if (Lbc == 0)      v = 0.5f*dt2*SG(Lrr, Lj);
                    else if (Lbc == 1) v = (Lrr == Lj) ? dt : 0.f;
                    else if (Lbc == 2) v = -dt*skewrowdot(Pm, Rm, Lrr, Lj)
                                           - 0.5f*dt2*skewrowdot(Vm, Rm, Lrr, Lj)
                                           - (dt3*(1.f/6.f))*sgR(Rm, Lrr, Lj);
                    else               v = -0.5f*dt2*Rm[Lrr*3+Lj];
                }
                s.L[tid] = v;
                if (l2V) {
                    float v2 = 0.f;
                    if (L2bc == 0)      v2 = 0.5f*dt2*SG(2, L2j);
                    else if (L2bc == 1) v2 = (2 == L2j) ? dt : 0.f;
                    else if (L2bc == 2) v2 = -dt*skewrowdot(Pm, Rm, 2, L2j)
                                             - 0.5f*dt2*skewrowdot(Vm, Rm, 2, L2j)
                                             - (dt3*(1.f/6.f))*sgR(Rm, 2, L2j);
                    else                v2 = -0.5f*dt2*Rm[6+L2j];
                    s.L[96+tid] = v2;
                }
            }
            if (tid < 33) { *outP = s.mir[tid]; outP += outStride; }
            if (pfV && (i + 1 < N)) { pf = *pfP; pfP += pfStride; }
        }
        if (tid == 96) {
            const float gy0 = s.in[cur][1], gy1 = s.in[cur][2], gy2 = s.in[cur][3];
            const float ac0 = s.in[cur][4], ac1 = s.in[cur][5], ac2 = s.in[cur][6];
            omg[0] = gy0 - Bomg[0]; omg[1] = gy1 - Bomg[1]; omg[2] = gy2 - Bomg[2];
            float phi[3] = {omg[0]*dt, omg[1]*dt, omg[2]*dt};
            float a2 = phi[0]*phi[0] + phi[1]*phi[1] + phi[2]*phi[2];
            float c, sa, oc; so3c(a2, c, sa, oc);
            float E[9];
#pragma unroll
            for (int p = 0; p < 3; ++p)
#pragma unroll
                for (int q = 0; q < 3; ++q)
                    E[p*3+q] = ((p==q)?c:0.f) + oc*phi[p]*phi[q] + sa*skf(phi, p, q);
#pragma unroll
            for (int p = 0; p < 3; ++p)
#pragma unroll
                for (int q = 0; q < 3; ++q)
                    rn[p*3+q] = Rg[p*3+0]*E[0*3+q] + Rg[p*3+1]*E[1*3+q] + Rg[p*3+2]*E[2*3+q];
            float d0 = ac0 - Bacg[0], d1 = ac1 - Bacg[1], d2 = ac2 - Bacg[2];
            float acc[3];
#pragma unroll
            for (int q = 0; q < 3; ++q)
                acc[q] = Rg[q*3+0]*d0 + Rg[q*3+1]*d1 + Rg[q*3+2]*d2 + ((q==2)?GZ:0.f);
#pragma unroll
            for (int q = 0; q < 3; ++q) {
                vn[q]  = Vg[q] + acc[q]*dt;
                pn3[q] = Ppg[q] + Vg[q]*dt + 0.5f*acc[q]*dt2;
            }
#pragma unroll
            for (int q = 0; q < 3; ++q)
                vig[q] = rn[0*3+q]*vn[0] + rn[1*3+q]*vn[1] + rn[2*3+q]*vn[2];
            float h[24];
#pragma unroll
            for (int a = 0; a < 2; ++a)
#pragma unroll
                for (int j = 0; j < 3; ++j) {
                    h[a*12 + j]     = rn[j*3+0]*Rcig[a+1] + rn[j*3+1]*Rcig[3+a+1] + rn[j*3+2]*Rcig[6+a+1];
                    h[a*12 + 3 + j] = skf(Tcig, a+1, j);
                    h[a*12 + 6 + j] = Rcig[a+1]*skf(vig,0,j) + Rcig[3+a+1]*skf(vig,1,j) + Rcig[6+a+1]*skf(vig,2,j);
                    h[a*12 + 9 + j] = -skf(omg, a+1, j);
                }
            float Lv[9];
#pragma unroll
            for (int rr = 0; rr < 3; ++rr)
#pragma unroll
                for (int j = 0; j < 3; ++j)
                    Lv[rr*3+j] = -dt*skewrowdot(Vg, Rg, rr, j) - 0.5f*dt2*sgR(Rg, rr, j);
            float g[36];
#pragma unroll
            for (int a = 0; a < 2; ++a) {
                g[a*18+0] =  h[a*12+1]*(dt*GZ);
                g[a*18+1] = -h[a*12+0]*(dt*GZ);
                g[a*18+2] = 0.f;
#pragma unroll
                for (int j = 0; j < 3; ++j) g[a*18+3+j] = h[a*12+j];
#pragma unroll
                for (int j = 0; j < 3; ++j)
                    g[a*18+6+j] = h[a*12+3+j] + h[a*12+0]*Lv[j] + h[a*12+1]*Lv[3+j] + h[a*12+2]*Lv[6+j];
#pragma unroll
                for (int j = 0; j < 3; ++j)
                    g[a*18+9+j] = -dt*(h[a*12+0]*Rg[j] + h[a*12+1]*Rg[3+j] + h[a*12+2]*Rg[6+j]);
#pragma unroll
                for (int m = 12; m < 18; ++m) g[a*18+m] = h[a*12+m-6];
            }
#pragma unroll
            for (int m = 0; m < 36; ++m) s.G[m] = g[m];
            r2g[0] = -(Rcig[1]*vig[0] + Rcig[4]*vig[1] + Rcig[7]*vig[2] + (Tcig[2]*omg[0] - Tcig[0]*omg[2]));
            r2g[1] = -(Rcig[2]*vig[0] + Rcig[5]*vig[1] + Rcig[8]*vig[2] + (Tcig[0]*omg[1] - Tcig[1]*omg[0]));
        }
        __syncthreads();

        // ======== PHASE 2: T9 (tid<96) ; GA (tid 64..105) ========
        if (isMat) {
            float a = s.A[tid];
#pragma unroll
            for (int m = 0; m < 12; ++m) {
                int col = (m < 6) ? m : m + 3;
                a += s.L[t9aR12+m] * s.A[col*21 + t9aC];
            }
            s.T9[tid] = a;
            if (t9bV) {
                float b = s.A[t9k2];
#pragma unroll
                for (int m = 0; m < 12; ++m) {
                    int col = (m < 6) ? m : m + 3;
                    b += s.L[t9bR12+m] * s.A[col*21 + t9bC];
                }
                s.T9[t9k2] = b;
            }
        }
        if (gaV) {
            float acc = 0.f;
#pragma unroll
            for (int m = 0; m < 18; ++m) {
                int col = (m < 6) ? m : m + 3;
                acc += s.G[gaA*18+m] * s.A[col*21 + gaC];
            }
            s.GA[gaA*21+gaC] = acc;
        }
        __syncthreads();

        // ======== PHASE 3: Pn (tid<96) ; S (61..63) ; HP (86..127) ========
        if (isMat) {
#pragma unroll
            for (int sl = 0; sl < 5; ++sl) if (eV[sl]) {
                int e = tid + sl*96;
                float b = eT9f[sl] ? s.T9[e] : s.A[e];
                if (eJJ[sl] < 9) {
#pragma unroll
                    for (int m = 0; m < 12; ++m) {
                        int col = (m < 6) ? m : m + 3;
                        float brc = eT9f[sl] ? s.T9[eIIB[sl]+col] : s.A[eIIB[sl]+col];
                        b += brc * s.L[eJJ12[sl]+m];
                    }
                }
                s.Pn[e] = b;
            }
        }
        if (tid >= 61 && tid < 64) {
            int m = tid - 61;
            int a = (m == 2) ? 1 : 0;
            int bb = (m == 0) ? 0 : 1;
            float acc = 0.f;
#pragma unroll
            for (int mm = 0; mm < 18; ++mm) {
                int col = (mm < 6) ? mm : mm + 3;
                acc += s.GA[a*21+col] * s.G[bb*18+mm];
            }
            if (a == bb) acc += s.in[cur][7+a];
            s.S3[m] = acc;
        }
        if (hpV) {
            float hp = s.GA[hpA*21+hpC];
            if (hpC < 9) {
#pragma unroll
                for (int m = 0; m < 12; ++m) {
                    int col = (m < 6) ? m : m + 3;
                    hp += s.GA[hpA*21+col] * s.L[hpC*12+m];
                }
            }
            s.HP[hpA*21+hpC] = hp;
        }
        __syncthreads();

        // ======== PHASE 4: state chain (tid 96) ; prefetch STS ========
        if (pfV && (i + 1 < N)) s.in[cur^1][tid-64] = pf;
        if (tid == 96) {
            const float S00 = s.S3[0], S01 = s.S3[1], S11 = s.S3[2];
            const float idet = 1.f / (S00*S11 - S01*S01);
            const float Si00 = S11*idet, Si01 = -S01*idet, Si11 = S00*idet;
            const float w0 = Si00*r2g[0] + Si01*r2g[1];
            const float w1 = Si01*r2g[0] + Si11*r2g[1];
            float dx[21];
#pragma unroll
            for (int c2 = 0; c2 < 21; ++c2) dx[c2] = s.HP[c2]*w0 + s.HP[21+c2]*w1;
            float a2 = dx[0]*dx[0] + dx[1]*dx[1] + dx[2]*dx[2];
            float c, sa, oc; so3c(a2, c, sa, oc);
            float j1 = j1c(a2);
            float dR[9], J[9];
#pragma unroll
            for (int p = 0; p < 3; ++p)
#pragma unroll
                for (int q = 0; q < 3; ++q) {
                    dR[p*3+q] = ((p==q)?c:0.f)  + oc*dx[p]*dx[q] + sa*skf(dx, p, q);
                    J[p*3+q]  = ((p==q)?sa:0.f) + j1*dx[p]*dx[q] + oc*skf(dx, p, q);
                }
            float x0[3], x1[3];
#pragma unroll
            for (int q = 0; q < 3; ++q) {
                x0[q] = J[q*3+0]*dx[3] + J[q*3+1]*dx[4] + J[q*3+2]*dx[5];
                x1[q] = J[q*3+0]*dx[6] + J[q*3+1]*dx[7] + J[q*3+2]*dx[8];
            }
            float Ru[9];
#pragma unroll
            for (int p = 0; p < 3; ++p)
#pragma unroll
                for (int q = 0; q < 3; ++q)
                    Ru[p*3+q] = dR[p*3+0]*rn[0*3+q] + dR[p*3+1]*rn[1*3+q] + dR[p*3+2]*rn[2*3+q];
#pragma unroll
            for (int q = 0; q < 3; ++q) {
                float vu = dR[q*3+0]*vn[0]  + dR[q*3+1]*vn[1]  + dR[q*3+2]*vn[2]  + x0[q];
                float pu = dR[q*3+0]*pn3[0] + dR[q*3+1]*pn3[1] + dR[q*3+2]*pn3[2] + x1[q];
                Vg[q] = vu; Ppg[q] = pu;
                Bomg[q] += dx[9+q]; Bacg[q] += dx[12+q]; Tcig[q] += dx[18+q];
            }
#pragma unroll
            for (int m = 0; m < 9; ++m) Rg[m] = Ru[m];
            {
                float y0 = dx[15], y1 = dx[16], y2 = dx[17];
                float b2 = y0*y0 + y1*y1 + y2*y2;
                float cc2, sa2, oc2; so3c(b2, cc2, sa2, oc2);
                float yv[3] = {y0, y1, y2};
                float E2[9];
#pragma unroll
                for (int p = 0; p < 3; ++p)
#pragma unroll
                    for (int q = 0; q < 3; ++q)
                        E2[p*3+q] = ((p==q)?cc2:0.f) + oc2*yv[p]*yv[q] + sa2*skf(yv, p, q);
                float Rc[9];
#pragma unroll
                for (int p = 0; p < 3; ++p)
#pragma unroll
                    for (int q = 0; q < 3; ++q)
                        Rc[p*3+q] = E2[p*3+0]*Rcig[0*3+q] + E2[p*3+1]*Rcig[1*3+q] + E2[p*3+2]*Rcig[2*3+q];
#pragma unroll
                for (int m = 0; m < 9; ++m) Rcig[m] = Rc[m];
            }
            if (i % 100 == 0) {
                normrot(Rg);
                if (i % 1000 == 0) normrot(Rcig);
            }
#pragma unroll
            for (int m = 0; m < 9; ++m) s.mir[m] = Rg[m];
#pragma unroll
            for (int q = 0; q < 3; ++q) {
                s.mir[9+q] = Vg[q]; s.mir[12+q] = Ppg[q]; s.mir[15+q] = Bomg[q];
                s.mir[18+q] = Bacg[q]; s.mir[30+q] = Tcig[q];
            }
#pragma unroll
            for (int m = 0; m < 9; ++m) s.mir[21+m] = Rcig[m];
        }
        __syncthreads();
    }

    // ---------- epilogue: final state row ----------
    if (tid < 33) *outP = s.mir[tid];
}

extern "C" void kernel_launch(void* const* d_in, const int* in_sizes, int n_in,
                              void* d_out, int out_size) {
    const float* t    = (const float*)d_in[0];
    const float* u    = (const float*)d_in[1];
    const float* mcov = (const float*)d_in[2];
    const float* vmes = (const float*)d_in[3];
    const float* ang0 = (const float*)d_in[5];
    float* out = (float*)d_out;
    int N = in_sizes[0];
    iekf_kernel<<<1, NT>>>(t, u, mcov, vmes, ang0, out, N);
}

// round 10
// speedup vs baseline: 1.7694x; 1.1112x over previous
#include <cuda_runtime.h>
#include <math.h>

#define NT 128
#define GZ (-9.80665f)

struct SM {
    float A[441], Pn[441], T9[189], L[108];
    float G[36], GA[42], HP[42], S3[3];
    float mir[33];     // Rot 0-8, V 9-11, Pp 12-14, Bom 15-17, Bac 18-20, Rci 21-29, Tci 30-32
    float in[2][9];    // t, u[6], mcov[2]
};

__device__ __forceinline__ float skf(const float* w, int r, int c) {
    if (r == 0) return (c == 0) ? 0.f : ((c == 1) ? -w[2] : w[1]);
    if (r == 1) return (c == 0) ? w[2] : ((c == 1) ? 0.f : -w[0]);
    return (c == 0) ? -w[1] : ((c == 1) ? w[0] : 0.f);
}
__device__ __forceinline__ float skewrowdot(const float* w, const float* R, int rr, int j) {
    if (rr == 0) return -w[2]*R[3+j] + w[1]*R[6+j];
    if (rr == 1) return  w[2]*R[0+j] - w[0]*R[6+j];
    return -w[1]*R[0+j] + w[0]*R[3+j];
}
__device__ __forceinline__ float SG(int rr, int j) {
    if (rr == 0 && j == 1) return -GZ;
    if (rr == 1 && j == 0) return  GZ;
    return 0.f;
}
__device__ __forceinline__ float sgR(const float* R, int rr, int j) {
    if (rr == 0) return -GZ * R[3+j];
    if (rr == 1) return  GZ * R[0+j];
    return 0.f;
}
__device__ __forceinline__ void so3c(float a2, float& c, float& sa, float& oc) {
    c  = 1.f + a2*(-0.5f      + a2*((1.f/24.f)  + a2*(-1.f/720.f)));
    sa = 1.f + a2*((-1.f/6.f) + a2*((1.f/120.f) + a2*(-1.f/5040.f)));
    oc = 0.5f + a2*((-1.f/24.f) + a2*(1.f/720.f));
}
__device__ __forceinline__ float j1c(float a2) {
    return (1.f/6.f) + a2*((-1.f/120.f) + a2*(1.f/5040.f));
}
__device__ __forceinline__ void mm3(const float* A, const float* B, float* C) {
#pragma unroll
    for (int p = 0; p < 3; ++p)
#pragma unroll
        for (int q = 0; q < 3; ++q)
            C[p*3+q] = A[p*3+0]*B[0*3+q] + A[p*3+1]*B[1*3+q] + A[p*3+2]*B[2*3+q];
}
__device__ __forceinline__ void normrot(float* X) {
    for (int it = 0; it < 8; ++it) {
        float Y[9], Z[9];
#pragma unroll
        for (int p = 0; p < 3; ++p)
#pragma unroll
            for (int q = 0; q < 3; ++q)
                Y[p*3+q] = X[p*3+0]*X[q*3+0] + X[p*3+1]*X[q*3+1] + X[p*3+2]*X[q*3+2];
        mm3(Y, X, Z);
#pragma unroll
        for (int m = 0; m < 9; ++m) X[m] = 1.5f*X[m] - 0.5f*Z[m];
    }
}

__global__ void __launch_bounds__(NT, 1)
iekf_kernel(const float* __restrict__ t, const float* __restrict__ u,
            const float* __restrict__ mc, const float* __restrict__ vmes,
            const float* __restrict__ ang0, float* __restrict__ out, int N)
{
    __shared__ SM s;
    const int tid = threadIdx.x;
    const bool isMat = (tid < 96);
    const int ln = tid - 96;

    // ---------- matrix decodes: 5 slots/thread over 96 threads ----------
    bool eV[5]; int eII[5], eJJ[5], eJJT[5], eIIB[5], eJJ12[5];
    int eAm[5], eAr[5], eBrx[5]; float eAsc[5], eAqv[5]; bool eT9f[5];
#pragma unroll
    for (int sl = 0; sl < 5; ++sl) {
        int e = tid + sl*96;
        eV[sl] = isMat && (e < 441);
        int ii = 0, jj = 0;
        if (eV[sl]) { ii = e/21; jj = e - ii*21; }
        eII[sl]=ii; eJJ[sl]=jj; eJJT[sl]=jj*21+ii; eIIB[sl]=ii*21; eJJ12[sl]=jj*12;
        eT9f[sl] = (ii < 9);
        int am = 2, ar = 0, brx = 0; float asc = 0.f, aqv = 0.f;
        if (ii<3 && jj<3)                      { am=0; ar=ii*3;     brx=jj*3;     asc=0.001f; }
        else if (ii>=3&&ii<6&&jj>=3&&jj<6)     { am=0; ar=(ii-3)*3; brx=(jj-3)*3; asc=0.01f;  }
        else if (ii==jj) { am=1; aqv=(ii>=9&&ii<12)?6e-9f:(ii>=12&&ii<15)?2e-4f:(ii>=15)?1e-9f:0.f; }
        eAm[sl]=am; eAr[sl]=ar; eBrx[sl]=brx; eAsc[sl]=asc; eAqv[sl]=aqv;
    }
    // T9 slots
    const int t9aR12 = (tid/21)*12, t9aC = tid - (tid/21)*21;
    const int t9k2 = tid + 96; const bool t9bV = isMat && (t9k2 < 189);
    int t9bR12 = 0, t9bC = 0;
    if (t9bV) { int r = t9k2/21; t9bR12 = r*12; t9bC = t9k2 - r*21; }
    // L decodes
    int Lbrr = 0, Lrr = 0, Lbc = 0, Lj = 0;
    if (isMat) {
        int r = tid/12, cc = tid - r*12;
        Lbrr = r/3; Lrr = r - Lbrr*3; Lbc = cc/3; Lj = cc - Lbc*3;
    }
    const bool l2V = isMat && (tid < 12);
    const int L2bc = tid/3, L2j = tid - L2bc*3;
    // out pointers (tid<33)
    float* outP = out; int outStride = 0;
    if (tid < 9)       { outP = out + tid;              outStride = 9; }
    else if (tid < 12) { outP = out + 9*N  + (tid-9);   outStride = 3; }
    else if (tid < 15) { outP = out + 12*N + (tid-12);  outStride = 3; }
    else if (tid < 18) { outP = out + 15*N + (tid-15);  outStride = 3; }
    else if (tid < 21) { outP = out + 18*N + (tid-18);  outStride = 3; }
    else if (tid < 30) { outP = out + 21*N + (tid-21);  outStride = 9; }
    else if (tid < 33) { outP = out + 30*N + (tid-30);  outStride = 3; }
    // prefetch pointers (tid 64..72)
    const float* pfP = t; int pfStride = 0;
    const bool pfV = (tid >= 64 && tid < 73);
    if (pfV) {
        int q = tid - 64;
        if (q == 0)      { pfP = t  + 2;           pfStride = 1; }
        else if (q < 7)  { pfP = u  + 12 + (q-1);  pfStride = 6; }
        else             { pfP = mc + 4  + (q-7);  pfStride = 2; }
    }

    // chain-lane persistent registers (tid 96)
    float Rg[9], Vg[3], Ppg[3], Bomg[3], Bacg[3], Rcig[9], Tcig[3];
    float rn[9], vn[3], pn3[3], omg[3], vig[3], r2g[2];

    // ---------- prologue ----------
    float tprev = t[0];
    // Pn = P0, HP = 0, S3 = I  so first fused Joseph yields P0
#pragma unroll
    for (int sl = 0; sl < 5; ++sl) if (eV[sl]) {
        int e = tid + sl*96;
        int ii = eII[sl], jj = eJJ[sl];
        float pv = 0.f;
        if (ii == jj) {
            if (ii < 2) pv = 0.001f;
            else if (ii >= 3 && ii < 5) pv = 0.1f;
            else if (ii >= 9 && ii < 12) pv = 0.006f;
            else if (ii >= 12 && ii < 15) pv = 0.004f;
            else if (ii >= 15 && ii < 18) pv = 1e-6f;
            else if (ii >= 18) pv = 0.005f;
        }
        s.Pn[e] = pv;
    }
    if (tid < 42) s.HP[tid] = 0.f;
    if (tid == 42) { s.S3[0] = 1.f; s.S3[1] = 0.f; s.S3[2] = 1.f; }
    if (tid < 9) {
        float v;
        if (tid == 0) v = t[1];
        else if (tid < 7) v = u[6 + (tid-1)];
        else v = mc[2 + (tid-7)];
        s.in[1][tid] = v;
    }
    if (tid == 96) {
        float a0 = ang0[0], a1 = ang0[1], a2 = ang0[2];
        float cr = cosf(a0), sr = sinf(a0), cp = cosf(a1), sp = sinf(a1);
        float cy = cosf(a2), sy = sinf(a2);
        float Rx[9] = {1,0,0, 0,cr,-sr, 0,sr,cr};
        float Ry[9] = {cp,0,sp, 0,1,0, -sp,0,cp};
        float Rz[9] = {cy,-sy,0, sy,cy,0, 0,0,1};
        float T[9];
        mm3(Rz, Ry, T); mm3(T, Rx, Rg);
#pragma unroll
        for (int m = 0; m < 9; ++m) Rcig[m] = (m==0||m==4||m==8) ? 1.f : 0.f;
#pragma unroll
        for (int q = 0; q < 3; ++q) {
            Vg[q] = vmes[q]; Ppg[q] = 0.f; Bomg[q] = 0.f; Bacg[q] = 0.f; Tcig[q] = 0.f;
        }
#pragma unroll
        for (int m = 0; m < 9; ++m) s.mir[m] = Rg[m];
#pragma unroll
        for (int q = 0; q < 3; ++q) {
            s.mir[9+q] = Vg[q]; s.mir[12+q] = Ppg[q]; s.mir[15+q] = Bomg[q];
            s.mir[18+q] = Bacg[q]; s.mir[30+q] = Tcig[q];
        }
#pragma unroll
        for (int m = 0; m < 9; ++m) s.mir[21+m] = Rcig[m];
    }
    __syncthreads();

    // ---------- main loop ----------
    for (int i = 1; i < N; ++i) {
        const int cur = i & 1;
        const float tcv = s.in[cur][0];
        const float dt = tcv - tprev; tprev = tcv;
        const float dt2 = dt*dt;

        // ======== PHASE 1: mat {A=Joseph+gq, L, out, pf-LDG} ; w3 {measurement chain} ========
        float pf = 0.f;
        if (isMat) {
            const float dt3 = dt2*dt;
            const float S00 = s.S3[0], S01 = s.S3[1], S11 = s.S3[2];
            const float idet = 1.f / (S00*S11 - S01*S01);
            const float Si00 = S11*idet, Si01 = -S01*idet, Si11 = S00*idet;
#pragma unroll
            for (int sl = 0; sl < 5; ++sl) if (eV[sl]) {
                int e = tid + sl*96;
                float hp0i = s.HP[eII[sl]], hp1i = s.HP[21+eII[sl]];
                float hp0j = s.HP[eJJ[sl]], hp1j = s.HP[21+eJJ[sl]];
                float Ki0 = Si00*hp0i + Si01*hp1i, Ki1 = Si01*hp0i + Si11*hp1i;
                float Kj0 = Si00*hp0j + Si01*hp1j, Kj1 = Si01*hp0j + Si11*hp1j;
                float KSi0 = Ki0*S00 + Ki1*S01, KSi1 = Ki0*S01 + Ki1*S11;
                float pj = 0.5f*(s.Pn[e] + s.Pn[eJJT[sl]])
                         - (Ki0*hp0j + Ki1*hp1j) - (Kj0*hp0i + Kj1*hp1i)
                         + (KSi0*Kj0 + KSi1*Kj1);
                float gq = 0.f;
                if (eAm[sl] == 0) {
                    float d = s.mir[eAr[sl]]*s.mir[eBrx[sl]] + s.mir[eAr[sl]+1]*s.mir[eBrx[sl]+1]
                            + s.mir[eAr[sl]+2]*s.mir[eBrx[sl]+2];
                    gq = eAsc[sl] * dt2 * d;
                } else if (eAm[sl] == 1) gq = eAqv[sl] * dt2;
                s.A[e] = pj + gq;
            }
            {
                const float* Rm = s.mir; const float* Vm = s.mir + 9; const float* Pm = s.mir + 12;
                float v = 0.f;
                if (Lbrr == 0) {
                    if (Lbc == 2) v = -dt * Rm[Lrr*3+Lj];
                } else if (Lbrr == 1) {
                    if (Lbc == 0)      v = dt * SG(Lrr, Lj);
                    else if (Lbc == 2) v = -dt*skewrowdot(Vm, Rm, Lrr, Lj) - 0.5f*dt2*sgR(Rm, Lrr, Lj);
                    else if (Lbc == 3) v = -dt * Rm[Lrr*3+Lj];
                } else {
                    if (Lbc == 0)      v = 0.5f*dt2*SG(Lrr, Lj);
                    else if (Lbc == 1) v = (Lrr == Lj) ? dt : 0.f;
                    else if (Lbc == 2) v = -dt*skewrowdot(Pm, Rm, Lrr, Lj)
                                           - 0.5f*dt2*skewrowdot(Vm, Rm, Lrr, Lj)
                                           - (dt2*dt*(1.f/6.f))*sgR(Rm, Lrr, Lj);
                    else               v = -0.5f*dt2*Rm[Lrr*3+Lj];
                }
                s.L[tid] = v;
                if (l2V) {
                    float v2 = 0.f;
                    if (L2bc == 0)      v2 = 0.5f*dt2*SG(2, L2j);
                    else if (L2bc == 1) v2 = (2 == L2j) ? dt : 0.f;
                    else if (L2bc == 2) v2 = -dt*skewrowdot(Pm, Rm, 2, L2j)
                                             - 0.5f*dt2*skewrowdot(Vm, Rm, 2, L2j)
                                             - (dt3*(1.f/6.f))*sgR(Rm, 2, L2j);
                    else                v2 = -0.5f*dt2*Rm[6+L2j];
                    s.L[96+tid] = v2;
                }
            }
            if (tid < 33) { *outP = s.mir[tid]; outP += outStride; }
            if (pfV && (i + 1 < N)) { pf = *pfP; pfP += pfStride; }
        }
        if (tid == 96) {
            const float gy0 = s.in[cur][1], gy1 = s.in[cur][2], gy2 = s.in[cur][3];
            const float ac0 = s.in[cur][4], ac1 = s.in[cur][5], ac2 = s.in[cur][6];
            omg[0] = gy0 - Bomg[0]; omg[1] = gy1 - Bomg[1]; omg[2] = gy2 - Bomg[2];
            float phi[3] = {omg[0]*dt, omg[1]*dt, omg[2]*dt};
            float a2 = phi[0]*phi[0] + phi[1]*phi[1] + phi[2]*phi[2];
            float c, sa, oc; so3c(a2, c, sa, oc);
            float E[9];
#pragma unroll
            for (int p = 0; p < 3; ++p)
#pragma unroll
                for (int q = 0; q < 3; ++q)
                    E[p*3+q] = ((p==q)?c:0.f) + oc*phi[p]*phi[q] + sa*skf(phi, p, q);
#pragma unroll
            for (int p = 0; p < 3; ++p)
#pragma unroll
                for (int q = 0; q < 3; ++q)
                    rn[p*3+q] = Rg[p*3+0]*E[0*3+q] + Rg[p*3+1]*E[1*3+q] + Rg[p*3+2]*E[2*3+q];
            float d0 = ac0 - Bacg[0], d1 = ac1 - Bacg[1], d2 = ac2 - Bacg[2];
            float acc[3];
#pragma unroll
            for (int q = 0; q < 3; ++q)
                acc[q] = Rg[q*3+0]*d0 + Rg[q*3+1]*d1 + Rg[q*3+2]*d2 + ((q==2)?GZ:0.f);
#pragma unroll
            for (int q = 0; q < 3; ++q) {
                vn[q]  = Vg[q] + acc[q]*dt;
                pn3[q] = Ppg[q] + Vg[q]*dt + 0.5f*acc[q]*dt2;
            }
#pragma unroll
            for (int q = 0; q < 3; ++q)
                vig[q] = rn[0*3+q]*vn[0] + rn[1*3+q]*vn[1] + rn[2*3+q]*vn[2];
            float h[24];
#pragma unroll
            for (int a = 0; a < 2; ++a)
#pragma unroll
                for (int j = 0; j < 3; ++j) {
                    h[a*12 + j]     = rn[j*3+0]*Rcig[a+1] + rn[j*3+1]*Rcig[3+a+1] + rn[j*3+2]*Rcig[6+a+1];
                    h[a*12 + 3 + j] = skf(Tcig, a+1, j);
                    h[a*12 + 6 + j] = Rcig[a+1]*skf(vig,0,j) + Rcig[3+a+1]*skf(vig,1,j) + Rcig[6+a+1]*skf(vig,2,j);
                    h[a*12 + 9 + j] = -skf(omg, a+1, j);
                }
            float Lv[9];
#pragma unroll
            for (int rr = 0; rr < 3; ++rr)
#pragma unroll
                for (int j = 0; j < 3; ++j)
                    Lv[rr*3+j] = -dt*skewrowdot(Vg, Rg, rr, j) - 0.5f*dt2*sgR(Rg, rr, j);
            float g[36];
#pragma unroll
            for (int a = 0; a < 2; ++a) {
                g[a*18+0] =  h[a*12+1]*(dt*GZ);
                g[a*18+1] = -h[a*12+0]*(dt*GZ);
                g[a*18+2] = 0.f;
#pragma unroll
                for (int j = 0; j < 3; ++j) g[a*18+3+j] = h[a*12+j];
#pragma unroll
                for (int j = 0; j < 3; ++j)
                    g[a*18+6+j] = h[a*12+3+j] + h[a*12+0]*Lv[j] + h[a*12+1]*Lv[3+j] + h[a*12+2]*Lv[6+j];
#pragma unroll
                for (int j = 0; j < 3; ++j)
                    g[a*18+9+j] = -dt*(h[a*12+0]*Rg[j] + h[a*12+1]*Rg[3+j] + h[a*12+2]*Rg[6+j]);
#pragma unroll
                for (int m = 12; m < 18; ++m) g[a*18+m] = h[a*12+m-6];
            }
#pragma unroll
            for (int m = 0; m < 36; ++m) s.G[m] = g[m];
            r2g[0] = -(Rcig[1]*vig[0] + Rcig[4]*vig[1] + Rcig[7]*vig[2] + (Tcig[2]*omg[0] - Tcig[0]*omg[2]));
            r2g[1] = -(Rcig[2]*vig[0] + Rcig[5]*vig[1] + Rcig[8]*vig[2] + (Tcig[0]*omg[1] - Tcig[1]*omg[0]));
        }
        __syncthreads();

        // ======== PHASE 2: mat {T9} ; w3 {GA -> HP, S} ========
        if (isMat) {
            float a = s.A[tid];
#pragma unroll
            for (int m = 0; m < 12; ++m) {
                int col = (m < 6) ? m : m + 3;
                a += s.L[t9aR12+m] * s.A[col*21 + t9aC];
            }
            s.T9[tid] = a;
            if (t9bV) {
                float b = s.A[t9k2];
#pragma unroll
                for (int m = 0; m < 12; ++m) {
                    int col = (m < 6) ? m : m + 3;
                    b += s.L[t9bR12+m] * s.A[col*21 + t9bC];
                }
                s.T9[t9k2] = b;
            }
        } else {
            if (ln < 21) {
                float a0 = 0.f, a1 = 0.f;
#pragma unroll
                for (int m = 0; m < 18; ++m) {
                    int col = (m < 6) ? m : m + 3;
                    float av = s.A[col*21 + ln];
                    a0 += s.G[m]      * av;
                    a1 += s.G[18+m]   * av;
                }
                s.GA[ln] = a0; s.GA[21+ln] = a1;
            }
            __syncwarp();
            if (ln < 21) {
                float hp0 = s.GA[ln], hp1 = s.GA[21+ln];
                if (ln < 9) {
#pragma unroll
                    for (int m = 0; m < 12; ++m) {
                        int col = (m < 6) ? m : m + 3;
                        float lv = s.L[ln*12+m];
                        hp0 += s.GA[col]    * lv;
                        hp1 += s.GA[21+col] * lv;
                    }
                }
                s.HP[ln] = hp0; s.HP[21+ln] = hp1;
            } else if (ln < 24) {
                int m2 = ln - 21;
                int a = (m2 == 2) ? 1 : 0;
                int bb = (m2 == 0) ? 0 : 1;
                float acc = 0.f;
#pragma unroll
                for (int mm = 0; mm < 18; ++mm) {
                    int col = (mm < 6) ? mm : mm + 3;
                    acc += s.GA[a*21+col] * s.G[bb*18+mm];
                }
                if (a == bb) acc += s.in[cur][7+a];
                s.S3[m2] = acc;
            }
        }
        __syncthreads();

        // ======== PHASE 3: mat {Pn, pf-STS} ; w3 {state chain} ========
        if (isMat) {
#pragma unroll
            for (int sl = 0; sl < 5; ++sl) if (eV[sl]) {
                int e = tid + sl*96;
                float b = eT9f[sl] ? s.T9[e] : s.A[e];
                if (eJJ[sl] < 9) {
#pragma unroll
                    for (int m = 0; m < 12; ++m) {
                        int col = (m < 6) ? m : m + 3;
                        float brc = eT9f[sl] ? s.T9[eIIB[sl]+col] : s.A[eIIB[sl]+col];
                        b += brc * s.L[eJJ12[sl]+m];
                    }
                }
                s.Pn[e] = b;
            }
            if (pfV && (i + 1 < N)) s.in[cur^1][tid-64] = pf;
        }
        if (tid == 96) {
            const float S00 = s.S3[0], S01 = s.S3[1], S11 = s.S3[2];
            const float idet = 1.f / (S00*S11 - S01*S01);
            const float Si00 = S11*idet, Si01 = -S01*idet, Si11 = S00*idet;
            const float w0 = Si00*r2g[0] + Si01*r2g[1];
            const float w1 = Si01*r2g[0] + Si11*r2g[1];
            float dx[21];
#pragma unroll
            for (int c2 = 0; c2 < 21; ++c2) dx[c2] = s.HP[c2]*w0 + s.HP[21+c2]*w1;
            float a2 = dx[0]*dx[0] + dx[1]*dx[1] + dx[2]*dx[2];
            float c, sa, oc; so3c(a2, c, sa, oc);
            float j1 = j1c(a2);
            float dR[9], J[9];
#pragma unroll
            for (int p = 0; p < 3; ++p)
#pragma unroll
                for (int q = 0; q < 3; ++q) {
                    dR[p*3+q] = ((p==q)?c:0.f)  + oc*dx[p]*dx[q] + sa*skf(dx, p, q);
                    J[p*3+q]  = ((p==q)?sa:0.f) + j1*dx[p]*dx[q] + oc*skf(dx, p, q);
                }
            float x0[3], x1[3];
#pragma unroll
            for (int q = 0; q < 3; ++q) {
                x0[q] = J[q*3+0]*dx[3] + J[q*3+1]*dx[4] + J[q*3+2]*dx[5];
                x1[q] = J[q*3+0]*dx[6] + J[q*3+1]*dx[7] + J[q*3+2]*dx[8];
            }
            float Ru[9];
#pragma unroll
            for (int p = 0; p < 3; ++p)
#pragma unroll
                for (int q = 0; q < 3; ++q)
                    Ru[p*3+q] = dR[p*3+0]*rn[0*3+q] + dR[p*3+1]*rn[1*3+q] + dR[p*3+2]*rn[2*3+q];
#pragma unroll
            for (int q = 0; q < 3; ++q) {
                float vu = dR[q*3+0]*vn[0]  + dR[q*3+1]*vn[1]  + dR[q*3+2]*vn[2]  + x0[q];
                float pu = dR[q*3+0]*pn3[0] + dR[q*3+1]*pn3[1] + dR[q*3+2]*pn3[2] + x1[q];
                Vg[q] = vu; Ppg[q] = pu;
                Bomg[q] += dx[9+q]; Bacg[q] += dx[12+q]; Tcig[q] += dx[18+q];
            }
#pragma unroll
            for (int m = 0; m < 9; ++m) Rg[m] = Ru[m];
            {
                float y0 = dx[15], y1 = dx[16], y2 = dx[17];
                float b2 = y0*y0 + y1*y1 + y2*y2;
                float cc2, sa2, oc2; so3c(b2, cc2, sa2, oc2);
                float yv[3] = {y0, y1, y2};
                float E2[9];
#pragma unroll
                for (int p = 0; p < 3; ++p)
#pragma unroll
                    for (int q = 0; q < 3; ++q)
                        E2[p*3+q] = ((p==q)?cc2:0.f) + oc2*yv[p]*yv[q] + sa2*skf(yv, p, q);
                float Rc[9];
#pragma unroll
                for (int p = 0; p < 3; ++p)
#pragma unroll
                    for (int q = 0; q < 3; ++q)
                        Rc[p*3+q] = E2[p*3+0]*Rcig[0*3+q] + E2[p*3+1]*Rcig[1*3+q] + E2[p*3+2]*Rcig[2*3+q];
#pragma unroll
                for (int m = 0; m < 9; ++m) Rcig[m] = Rc[m];
            }
            if (i % 100 == 0) {
                normrot(Rg);
                if (i % 1000 == 0) normrot(Rcig);
            }
#pragma unroll
            for (int m = 0; m < 9; ++m) s.mir[m] = Rg[m];
#pragma unroll
            for (int q = 0; q < 3; ++q) {
                s.mir[9+q] = Vg[q]; s.mir[12+q] = Ppg[q]; s.mir[15+q] = Bomg[q];
                s.mir[18+q] = Bacg[q]; s.mir[30+q] = Tcig[q];
            }
#pragma unroll
            for (int m = 0; m < 9; ++m) s.mir[21+m] = Rcig[m];
        }
        __syncthreads();
    }

    // ---------- epilogue: final state row ----------
    if (tid < 33) *outP = s.mir[tid];
}

extern "C" void kernel_launch(void* const* d_in, const int* in_sizes, int n_in,
                              void* d_out, int out_size) {
    const float* t    = (const float*)d_in[0];
    const float* u    = (const float*)d_in[1];
    const float* mcov = (const float*)d_in[2];
    const float* vmes = (const float*)d_in[3];
    const float* ang0 = (const float*)d_in[5];
    float* out = (float*)d_out;
    int N = in_sizes[0];
    iekf_kernel<<<1, NT>>>(t, u, mcov, vmes, ang0, out, N);
}

// round 11
// speedup vs baseline: 1.8467x; 1.0437x over previous
#include <cuda_runtime.h>
#include <math.h>

#define NT 128
#define GZ (-9.80665f)

struct SM {
    float A[441], Pn[441], T9[189], L[108];
    float G[36], GA[42], HP[42], S3[3];
    float Rotn[9], vi3[3], Om3[3], r2s[2], dxs[21];
    float mir[33];     // Rot 0-8, V 9-11, Pp 12-14, Bom 15-17, Bac 18-20, Rci 21-29, Tci 30-32
    float in[2][9];    // t, u[6], mcov[2]
};

__device__ __forceinline__ float skf(const float* w, int r, int c) {
    if (r == 0) return (c == 0) ? 0.f : ((c == 1) ? -w[2] : w[1]);
    if (r == 1) return (c == 0) ? w[2] : ((c == 1) ? 0.f : -w[0]);
    return (c == 0) ? -w[1] : ((c == 1) ? w[0] : 0.f);
}
__device__ __forceinline__ float skewrowdot(const float* w, const float* R, int rr, int j) {
    if (rr == 0) return -w[2]*R[3+j] + w[1]*R[6+j];
    if (rr == 1) return  w[2]*R[0+j] - w[0]*R[6+j];
    return -w[1]*R[0+j] + w[0]*R[3+j];
}
__device__ __forceinline__ float SG(int rr, int j) {
    if (rr == 0 && j == 1) return -GZ;
    if (rr == 1 && j == 0) return  GZ;
    return 0.f;
}
__device__ __forceinline__ float sgR(const float* R, int rr, int j) {
    if (rr == 0) return -GZ * R[3+j];
    if (rr == 1) return  GZ * R[0+j];
    return 0.f;
}
__device__ __forceinline__ void so3c(float a2, float& c, float& sa, float& oc) {
    c  = 1.f + a2*(-0.5f      + a2*((1.f/24.f)  + a2*(-1.f/720.f)));
    sa = 1.f + a2*((-1.f/6.f) + a2*((1.f/120.f) + a2*(-1.f/5040.f)));
    oc = 0.5f + a2*((-1.f/24.f) + a2*(1.f/720.f));
}
__device__ __forceinline__ float j1c(float a2) {
    return (1.f/6.f) + a2*((-1.f/120.f) + a2*(1.f/5040.f));
}
__device__ __forceinline__ void mm3(const float* A, const float* B, float* C) {
#pragma unroll
    for (int p = 0; p < 3; ++p)
#pragma unroll
        for (int q = 0; q < 3; ++q)
            C[p*3+q] = A[p*3+0]*B[0*3+q] + A[p*3+1]*B[1*3+q] + A[p*3+2]*B[2*3+q];
}
__device__ __forceinline__ void normrot(float* X) {
    for (int it = 0; it < 8; ++it) {
        float Y[9], Z[9];
#pragma unroll
        for (int p = 0; p < 3; ++p)
#pragma unroll
            for (int q = 0; q < 3; ++q)
                Y[p*3+q] = X[p*3+0]*X[q*3+0] + X[p*3+1]*X[q*3+1] + X[p*3+2]*X[q*3+2];
        mm3(Y, X, Z);
#pragma unroll
        for (int m = 0; m < 9; ++m) X[m] = 1.5f*X[m] - 0.5f*Z[m];
    }
}

__global__ void __launch_bounds__(NT, 1)
iekf_kernel(const float* __restrict__ t, const float* __restrict__ u,
            const float* __restrict__ mc, const float* __restrict__ vmes,
            const float* __restrict__ ang0, float* __restrict__ out, int N)
{
    __shared__ SM s;
    const int tid = threadIdx.x;
    const bool isMat = (tid < 96);
    const int ln = tid - 96;

    // ---------- matrix decodes: 5 slots/thread over 96 threads ----------
    bool eV[5]; int eII[5], eJJ[5], eJJT[5], eIIB[5], eJJ12[5];
    int eAm[5], eAr[5], eBrx[5]; float eAsc[5], eAqv[5]; bool eT9f[5];
#pragma unroll
    for (int sl = 0; sl < 5; ++sl) {
        int e = tid + sl*96;
        eV[sl] = isMat && (e < 441);
        int ii = 0, jj = 0;
        if (eV[sl]) { ii = e/21; jj = e - ii*21; }
        eII[sl]=ii; eJJ[sl]=jj; eJJT[sl]=jj*21+ii; eIIB[sl]=ii*21; eJJ12[sl]=jj*12;
        eT9f[sl] = (ii < 9);
        int am = 2, ar = 0, brx = 0; float asc = 0.f, aqv = 0.f;
        if (ii<3 && jj<3)                      { am=0; ar=ii*3;     brx=jj*3;     asc=0.001f; }
        else if (ii>=3&&ii<6&&jj>=3&&jj<6)     { am=0; ar=(ii-3)*3; brx=(jj-3)*3; asc=0.01f;  }
        else if (ii==jj) { am=1; aqv=(ii>=9&&ii<12)?6e-9f:(ii>=12&&ii<15)?2e-4f:(ii>=15)?1e-9f:0.f; }
        eAm[sl]=am; eAr[sl]=ar; eBrx[sl]=brx; eAsc[sl]=asc; eAqv[sl]=aqv;
    }
    // T9 slots
    const int t9aR12 = (tid/21)*12, t9aC = tid - (tid/21)*21;
    const int t9k2 = tid + 96; const bool t9bV = isMat && (t9k2 < 189);
    int t9bR12 = 0, t9bC = 0;
    if (t9bV) { int r = t9k2/21; t9bR12 = r*12; t9bC = t9k2 - r*21; }
    // L decodes
    int Lbrr = 0, Lrr = 0, Lbc = 0, Lj = 0;
    if (isMat) {
        int r = tid/12, cc = tid - r*12;
        Lbrr = r/3; Lrr = r - Lbrr*3; Lbc = cc/3; Lj = cc - Lbc*3;
    }
    const bool l2V = isMat && (tid < 12);
    const int L2bc = tid/3, L2j = tid - L2bc*3;
    // out pointers (tid<33)
    float* outP = out; int outStride = 0;
    if (tid < 9)       { outP = out + tid;              outStride = 9; }
    else if (tid < 12) { outP = out + 9*N  + (tid-9);   outStride = 3; }
    else if (tid < 15) { outP = out + 12*N + (tid-12);  outStride = 3; }
    else if (tid < 18) { outP = out + 15*N + (tid-15);  outStride = 3; }
    else if (tid < 21) { outP = out + 18*N + (tid-18);  outStride = 3; }
    else if (tid < 30) { outP = out + 21*N + (tid-21);  outStride = 9; }
    else if (tid < 33) { outP = out + 30*N + (tid-30);  outStride = 3; }
    // prefetch pointers (tid 64..72)
    const float* pfP = t; int pfStride = 0;
    const bool pfV = (tid >= 64 && tid < 73);
    if (pfV) {
        int q = tid - 64;
        if (q == 0)      { pfP = t  + 2;           pfStride = 1; }
        else if (q < 7)  { pfP = u  + 12 + (q-1);  pfStride = 6; }
        else             { pfP = mc + 4  + (q-7);  pfStride = 2; }
    }

    // chain-lane persistent registers (ln==0, i.e. tid 96)
    float Rg[9], Vg[3], Ppg[3], Bomg[3], Bacg[3], Rcig[9], Tcig[3];
    float rn[9], vn[3], pn3[3];

    // ---------- prologue ----------
    float tprev = t[0];
#pragma unroll
    for (int sl = 0; sl < 5; ++sl) if (eV[sl]) {
        int e = tid + sl*96;
        int ii = eII[sl], jj = eJJ[sl];
        float pv = 0.f;
        if (ii == jj) {
            if (ii < 2) pv = 0.001f;
            else if (ii >= 3 && ii < 5) pv = 0.1f;
            else if (ii >= 9 && ii < 12) pv = 0.006f;
            else if (ii >= 12 && ii < 15) pv = 0.004f;
            else if (ii >= 15 && ii < 18) pv = 1e-6f;
            else if (ii >= 18) pv = 0.005f;
        }
        s.Pn[e] = pv;
    }
    if (tid < 42) s.HP[tid] = 0.f;
    if (tid == 42) { s.S3[0] = 1.f; s.S3[1] = 0.f; s.S3[2] = 1.f; }
    if (tid < 9) {
        float v;
        if (tid == 0) v = t[1];
        else if (tid < 7) v = u[6 + (tid-1)];
        else v = mc[2 + (tid-7)];
        s.in[1][tid] = v;
    }
    if (tid == 96) {
        float a0 = ang0[0], a1 = ang0[1], a2 = ang0[2];
        float cr = cosf(a0), sr = sinf(a0), cp = cosf(a1), sp = sinf(a1);
        float cy = cosf(a2), sy = sinf(a2);
        float Rx[9] = {1,0,0, 0,cr,-sr, 0,sr,cr};
        float Ry[9] = {cp,0,sp, 0,1,0, -sp,0,cp};
        float Rz[9] = {cy,-sy,0, sy,cy,0, 0,0,1};
        float T[9];
        mm3(Rz, Ry, T); mm3(T, Rx, Rg);
#pragma unroll
        for (int m = 0; m < 9; ++m) Rcig[m] = (m==0||m==4||m==8) ? 1.f : 0.f;
#pragma unroll
        for (int q = 0; q < 3; ++q) {
            Vg[q] = vmes[q]; Ppg[q] = 0.f; Bomg[q] = 0.f; Bacg[q] = 0.f; Tcig[q] = 0.f;
        }
#pragma unroll
        for (int m = 0; m < 9; ++m) s.mir[m] = Rg[m];
#pragma unroll
        for (int q = 0; q < 3; ++q) {
            s.mir[9+q] = Vg[q]; s.mir[12+q] = Ppg[q]; s.mir[15+q] = Bomg[q];
            s.mir[18+q] = Bacg[q]; s.mir[30+q] = Tcig[q];
        }
#pragma unroll
        for (int m = 0; m < 9; ++m) s.mir[21+m] = Rcig[m];
    }
    __syncthreads();

    // ---------- main loop ----------
    for (int i = 1; i < N; ++i) {
        const int cur = i & 1;
        const float tcv = s.in[cur][0];
        const float dt = tcv - tprev; tprev = tcv;
        const float dt2 = dt*dt;

        // ======== PHASE 1: mat {A=Joseph+gq, L, out, pf-LDG} ; w3 {meas chain split} ========
        float pf = 0.f;
        if (isMat) {
            const float dt3 = dt2*dt;
            const float S00 = s.S3[0], S01 = s.S3[1], S11 = s.S3[2];
            const float idet = 1.f / (S00*S11 - S01*S01);
            const float Si00 = S11*idet, Si01 = -S01*idet, Si11 = S00*idet;
#pragma unroll
            for (int sl = 0; sl < 5; ++sl) if (eV[sl]) {
                int e = tid + sl*96;
                float hp0i = s.HP[eII[sl]], hp1i = s.HP[21+eII[sl]];
                float hp0j = s.HP[eJJ[sl]], hp1j = s.HP[21+eJJ[sl]];
                float Ki0 = Si00*hp0i + Si01*hp1i, Ki1 = Si01*hp0i + Si11*hp1i;
                float Kj0 = Si00*hp0j + Si01*hp1j, Kj1 = Si01*hp0j + Si11*hp1j;
                float KSi0 = Ki0*S00 + Ki1*S01, KSi1 = Ki0*S01 + Ki1*S11;
                float pj = 0.5f*(s.Pn[e] + s.Pn[eJJT[sl]])
                         - (Ki0*hp0j + Ki1*hp1j) - (Kj0*hp0i + Kj1*hp1i)
                         + (KSi0*Kj0 + KSi1*Kj1);
                float gq = 0.f;
                if (eAm[sl] == 0) {
                    float d = s.mir[eAr[sl]]*s.mir[eBrx[sl]] + s.mir[eAr[sl]+1]*s.mir[eBrx[sl]+1]
                            + s.mir[eAr[sl]+2]*s.mir[eBrx[sl]+2];
                    gq = eAsc[sl] * dt2 * d;
                } else if (eAm[sl] == 1) gq = eAqv[sl] * dt2;
                s.A[e] = pj + gq;
            }
            {
                const float* Rm = s.mir; const float* Vm = s.mir + 9; const float* Pm = s.mir + 12;
                float v = 0.f;
                if (Lbrr == 0) {
                    if (Lbc == 2) v = -dt * Rm[Lrr*3+Lj];
                } else if (Lbrr == 1) {
                    if (Lbc == 0)      v = dt * SG(Lrr, Lj);
                    else if (Lbc == 2) v = -dt*skewrowdot(Vm, Rm, Lrr, Lj) - 0.5f*dt2*sgR(Rm, Lrr, Lj);
                    else if (Lbc == 3) v = -dt * Rm[Lrr*3+Lj];
                } else {
                    if (Lbc == 0)      v = 0.5f*dt2*SG(Lrr, Lj);
                    else if (Lbc == 1) v = (Lrr == Lj) ? dt : 0.f;
                    else if (Lbc == 2) v = -dt*skewrowdot(Pm, Rm, Lrr, Lj)
                                           - 0.5f*dt2*skewrowdot(Vm, Rm, Lrr, Lj)
                                           - (dt3*(1.f/6.f))*sgR(Rm, Lrr, Lj);
                    else               v = -0.5f*dt2*Rm[Lrr*3+Lj];
                }
                s.L[tid] = v;
                if (l2V) {
                    float v2 = 0.f;
                    if (L2bc == 0)      v2 = 0.5f*dt2*SG(2, L2j);
                    else if (L2bc == 1) v2 = (2 == L2j) ? dt : 0.f;
                    else if (L2bc == 2) v2 = -dt*skewrowdot(Pm, Rm, 2, L2j)
                                             - 0.5f*dt2*skewrowdot(Vm, Rm, 2, L2j)
                                             - (dt3*(1.f/6.f))*sgR(Rm, 2, L2j);
                    else                v2 = -0.5f*dt2*Rm[6+L2j];
                    s.L[96+tid] = v2;
                }
            }
            if (tid < 33) { *outP = s.mir[tid]; outP += outStride; }
            if (pfV && (i + 1 < N)) { pf = *pfP; pfP += pfStride; }
        } else {
            // ---- stage 1 (lane 0): omg, rn, vn, pn3, vig ----
            if (ln == 0) {
                const float gy0 = s.in[cur][1], gy1 = s.in[cur][2], gy2 = s.in[cur][3];
                const float ac0 = s.in[cur][4], ac1 = s.in[cur][5], ac2 = s.in[cur][6];
                float om0 = gy0 - Bomg[0], om1 = gy1 - Bomg[1], om2 = gy2 - Bomg[2];
                s.Om3[0] = om0; s.Om3[1] = om1; s.Om3[2] = om2;
                float phi[3] = {om0*dt, om1*dt, om2*dt};
                float a2 = phi[0]*phi[0] + phi[1]*phi[1] + phi[2]*phi[2];
                float c, sa, oc; so3c(a2, c, sa, oc);
                float E[9];
#pragma unroll
                for (int p = 0; p < 3; ++p)
#pragma unroll
                    for (int q = 0; q < 3; ++q)
                        E[p*3+q] = ((p==q)?c:0.f) + oc*phi[p]*phi[q] + sa*skf(phi, p, q);
#pragma unroll
                for (int p = 0; p < 3; ++p)
#pragma unroll
                    for (int q = 0; q < 3; ++q) {
                        rn[p*3+q] = Rg[p*3+0]*E[0*3+q] + Rg[p*3+1]*E[1*3+q] + Rg[p*3+2]*E[2*3+q];
                        s.Rotn[p*3+q] = rn[p*3+q];
                    }
                float d0 = ac0 - Bacg[0], d1 = ac1 - Bacg[1], d2 = ac2 - Bacg[2];
                float acc[3];
#pragma unroll
                for (int q = 0; q < 3; ++q)
                    acc[q] = Rg[q*3+0]*d0 + Rg[q*3+1]*d1 + Rg[q*3+2]*d2 + ((q==2)?GZ:0.f);
#pragma unroll
                for (int q = 0; q < 3; ++q) {
                    vn[q]  = Vg[q] + acc[q]*dt;
                    pn3[q] = Ppg[q] + Vg[q]*dt + 0.5f*acc[q]*dt2;
                }
#pragma unroll
                for (int q = 0; q < 3; ++q)
                    s.vi3[q] = rn[0*3+q]*vn[0] + rn[1*3+q]*vn[1] + rn[2*3+q]*vn[2];
            }
            __syncwarp();
            // ---- stage 2 (lanes 0,1): h/g row a, r2[a] ----
            if (ln < 2) {
                const int a = ln;
                const float* Rm  = s.mir;        // Rot
                const float* Vm  = s.mir + 9;    // V
                const float* Rc  = s.mir + 21;   // Rci
                const float* Tc  = s.mir + 30;   // Tci
                const float* rns = s.Rotn;
                const float* vis = s.vi3;
                const float* oms = s.Om3;
                float h[12];
#pragma unroll
                for (int j = 0; j < 3; ++j) {
                    h[j]     = rns[j*3+0]*Rc[a+1] + rns[j*3+1]*Rc[3+a+1] + rns[j*3+2]*Rc[6+a+1];
                    h[3+j]   = skf(Tc, a+1, j);
                    h[6+j]   = Rc[a+1]*skf(vis,0,j) + Rc[3+a+1]*skf(vis,1,j) + Rc[6+a+1]*skf(vis,2,j);
                    h[9+j]   = -skf(oms, a+1, j);
                }
                float Lv[9];
#pragma unroll
                for (int rr = 0; rr < 3; ++rr)
#pragma unroll
                    for (int j = 0; j < 3; ++j)
                        Lv[rr*3+j] = -dt*skewrowdot(Vm, Rm, rr, j) - 0.5f*dt2*sgR(Rm, rr, j);
                float g[18];
                g[0] =  h[1]*(dt*GZ);
                g[1] = -h[0]*(dt*GZ);
                g[2] = 0.f;
#pragma unroll
                for (int j = 0; j < 3; ++j) g[3+j] = h[j];
#pragma unroll
                for (int j = 0; j < 3; ++j)
                    g[6+j] = h[3+j] + h[0]*Lv[j] + h[1]*Lv[3+j] + h[2]*Lv[6+j];
#pragma unroll
                for (int j = 0; j < 3; ++j)
                    g[9+j] = -dt*(h[0]*Rm[j] + h[1]*Rm[3+j] + h[2]*Rm[6+j]);
#pragma unroll
                for (int m = 12; m < 18; ++m) g[m] = h[m-6];
#pragma unroll
                for (int m = 0; m < 18; ++m) s.G[a*18+m] = g[m];
                float cxa = (a==0) ? (Tc[2]*oms[0] - Tc[0]*oms[2])
                                   : (Tc[0]*oms[1] - Tc[1]*oms[0]);
                s.r2s[a] = -(Rc[a+1]*vis[0] + Rc[3+a+1]*vis[1] + Rc[6+a+1]*vis[2] + cxa);
            }
        }
        __syncthreads();

        // ======== PHASE 2: mat {T9} ; w3 {GA -> HP, S} ========
        if (isMat) {
            float a = s.A[tid];
#pragma unroll
            for (int m = 0; m < 12; ++m) {
                int col = (m < 6) ? m : m + 3;
                a += s.L[t9aR12+m] * s.A[col*21 + t9aC];
            }
            s.T9[tid] = a;
            if (t9bV) {
                float b = s.A[t9k2];
#pragma unroll
                for (int m = 0; m < 12; ++m) {
                    int col = (m < 6) ? m : m + 3;
                    b += s.L[t9bR12+m] * s.A[col*21 + t9bC];
                }
                s.T9[t9k2] = b;
            }
        } else {
            if (ln < 21) {
                float a0 = 0.f, a1 = 0.f;
#pragma unroll
                for (int m = 0; m < 18; ++m) {
                    int col = (m < 6) ? m : m + 3;
                    float av = s.A[col*21 + ln];
                    a0 += s.G[m]      * av;
                    a1 += s.G[18+m]   * av;
                }
                s.GA[ln] = a0; s.GA[21+ln] = a1;
            }
            __syncwarp();
            if (ln < 21) {
                float hp0 = s.GA[ln], hp1 = s.GA[21+ln];
                if (ln < 9) {
#pragma unroll
                    for (int m = 0; m < 12; ++m) {
                        int col = (m < 6) ? m : m + 3;
                        float lv = s.L[ln*12+m];
                        hp0 += s.GA[col]    * lv;
                        hp1 += s.GA[21+col] * lv;
                    }
                }
                s.HP[ln] = hp0; s.HP[21+ln] = hp1;
            } else if (ln < 24) {
                int m2 = ln - 21;
                int a = (m2 == 2) ? 1 : 0;
                int bb = (m2 == 0) ? 0 : 1;
                float acc = 0.f;
#pragma unroll
                for (int mm = 0; mm < 18; ++mm) {
                    int col = (mm < 6) ? mm : mm + 3;
                    acc += s.GA[a*21+col] * s.G[bb*18+mm];
                }
                if (a == bb) acc += s.in[cur][7+a];
                s.S3[m2] = acc;
            }
        }
        __syncthreads();

        // ======== PHASE 3: mat {Pn, pf-STS} ; w3 {dx precompute + state chain} ========
        if (isMat) {
#pragma unroll
            for (int sl = 0; sl < 5; ++sl) if (eV[sl]) {
                int e = tid + sl*96;
                float b = eT9f[sl] ? s.T9[e] : s.A[e];
                if (eJJ[sl] < 9) {
#pragma unroll
                    for (int m = 0; m < 12; ++m) {
                        int col = (m < 6) ? m : m + 3;
                        float brc = eT9f[sl] ? s.T9[eIIB[sl]+col] : s.A[eIIB[sl]+col];
                        b += brc * s.L[eJJ12[sl]+m];
                    }
                }
                s.Pn[e] = b;
            }
            if (pfV && (i + 1 < N)) s.in[cur^1][tid-64] = pf;
        } else {
            if (ln < 21) {
                const float S00 = s.S3[0], S01 = s.S3[1], S11 = s.S3[2];
                const float idet = 1.f / (S00*S11 - S01*S01);
                const float r0 = s.r2s[0], r1 = s.r2s[1];
                const float w0 = idet*( S11*r0 - S01*r1);
                const float w1 = idet*(-S01*r0 + S00*r1);
                s.dxs[ln] = s.HP[ln]*w0 + s.HP[21+ln]*w1;
            }
            __syncwarp();
            if (ln == 0) {
                float dx[21];
#pragma unroll
                for (int c2 = 0; c2 < 21; ++c2) dx[c2] = s.dxs[c2];
                float a2 = dx[0]*dx[0] + dx[1]*dx[1] + dx[2]*dx[2];
                float c, sa, oc; so3c(a2, c, sa, oc);
                float j1 = j1c(a2);
                float dR[9], J[9];
#pragma unroll
                for (int p = 0; p < 3; ++p)
#pragma unroll
                    for (int q = 0; q < 3; ++q) {
                        dR[p*3+q] = ((p==q)?c:0.f)  + oc*dx[p]*dx[q] + sa*skf(dx, p, q);
                        J[p*3+q]  = ((p==q)?sa:0.f) + j1*dx[p]*dx[q] + oc*skf(dx, p, q);
                    }
                float x0[3], x1[3];
#pragma unroll
                for (int q = 0; q < 3; ++q) {
                    x0[q] = J[q*3+0]*dx[3] + J[q*3+1]*dx[4] + J[q*3+2]*dx[5];
                    x1[q] = J[q*3+0]*dx[6] + J[q*3+1]*dx[7] + J[q*3+2]*dx[8];
                }
                float Ru[9];
#pragma unroll
                for (int p = 0; p < 3; ++p)
#pragma unroll
                    for (int q = 0; q < 3; ++q)
                        Ru[p*3+q] = dR[p*3+0]*rn[0*3+q] + dR[p*3+1]*rn[1*3+q] + dR[p*3+2]*rn[2*3+q];
#pragma unroll
                for (int q = 0; q < 3; ++q) {
                    float vu = dR[q*3+0]*vn[0]  + dR[q*3+1]*vn[1]  + dR[q*3+2]*vn[2]  + x0[q];
                    float pu = dR[q*3+0]*pn3[0] + dR[q*3+1]*pn3[1] + dR[q*3+2]*pn3[2] + x1[q];
                    Vg[q] = vu; Ppg[q] = pu;
                    Bomg[q] += dx[9+q]; Bacg[q] += dx[12+q]; Tcig[q] += dx[18+q];
                }
#pragma unroll
                for (int m = 0; m < 9; ++m) Rg[m] = Ru[m];
                {
                    float y0 = dx[15], y1 = dx[16], y2 = dx[17];
                    float b2 = y0*y0 + y1*y1 + y2*y2;
                    float cc2, sa2, oc2; so3c(b2, cc2, sa2, oc2);
                    float yv[3] = {y0, y1, y2};
                    float E2[9];
#pragma unroll
                    for (int p = 0; p < 3; ++p)
#pragma unroll
                        for (int q = 0; q < 3; ++q)
                            E2[p*3+q] = ((p==q)?cc2:0.f) + oc2*yv[p]*yv[q] + sa2*skf(yv, p, q);
                    float Rc2[9];
#pragma unroll
                    for (int p = 0; p < 3; ++p)
#pragma unroll
                        for (int q = 0; q < 3; ++q)
                            Rc2[p*3+q] = E2[p*3+0]*Rcig[0*3+q] + E2[p*3+1]*Rcig[1*3+q] + E2[p*3+2]*Rcig[2*3+q];
#pragma unroll
                    for (int m = 0; m < 9; ++m) Rcig[m] = Rc2[m];
                }
                if (i % 100 == 0) {
                    normrot(Rg);
                    if (i % 1000 == 0) normrot(Rcig);
                }
#pragma unroll
                for (int m = 0; m < 9; ++m) s.mir[m] = Rg[m];
#pragma unroll
                for (int q = 0; q < 3; ++q) {
                    s.mir[9+q] = Vg[q]; s.mir[12+q] = Ppg[q]; s.mir[15+q] = Bomg[q];
                    s.mir[18+q] = Bacg[q]; s.mir[30+q] = Tcig[q];
                }
#pragma unroll
                for (int m = 0; m < 9; ++m) s.mir[21+m] = Rcig[m];
            }
        }
        __syncthreads();
    }

    // ---------- epilogue: final state row ----------
    if (tid < 33) *outP = s.mir[tid];
}

extern "C" void kernel_launch(void* const* d_in, const int* in_sizes, int n_in,
                              void* d_out, int out_size) {
    const float* t    = (const float*)d_in[0];
    const float* u    = (const float*)d_in[1];
    const float* mcov = (const float*)d_in[2];
    const float* vmes = (const float*)d_in[3];
    const float* ang0 = (const float*)d_in[5];
    float* out = (float*)d_out;
    int N = in_sizes[0];
    iekf_kernel<<<1, NT>>>(t, u, mcov, vmes, ang0, out, N);
}

// round 12
// speedup vs baseline: 2.0588x; 1.1149x over previous
#include <cuda_runtime.h>
#include <math.h>

#define NT 128
#define GZ (-9.80665f)

struct SM {
    float A[441], Pn[441], T9[189], L[108];
    float G[36], GA[42], HP[42], S3[3];
    float Rotn[9], vi3[3], Om3[3], r2s[2], dxs[21];
    float mir[33];     // Rot 0-8, V 9-11, Pp 12-14, Bom 15-17, Bac 18-20, Rci 21-29, Tci 30-32
    float in[2][9];    // t, u[6], mcov[2]
};

__device__ __forceinline__ float skf(const float* w, int r, int c) {
    if (r == 0) return (c == 0) ? 0.f : ((c == 1) ? -w[2] : w[1]);
    if (r == 1) return (c == 0) ? w[2] : ((c == 1) ? 0.f : -w[0]);
    return (c == 0) ? -w[1] : ((c == 1) ? w[0] : 0.f);
}
__device__ __forceinline__ float skewrowdot(const float* w, const float* R, int rr, int j) {
    if (rr == 0) return -w[2]*R[3+j] + w[1]*R[6+j];
    if (rr == 1) return  w[2]*R[0+j] - w[0]*R[6+j];
    return -w[1]*R[0+j] + w[0]*R[3+j];
}
__device__ __forceinline__ float SG(int rr, int j) {
    if (rr == 0 && j == 1) return -GZ;
    if (rr == 1 && j == 0) return  GZ;
    return 0.f;
}
__device__ __forceinline__ float sgR(const float* R, int rr, int j) {
    if (rr == 0) return -GZ * R[3+j];
    if (rr == 1) return  GZ * R[0+j];
    return 0.f;
}
__device__ __forceinline__ void so3c(float a2, float& c, float& sa, float& oc) {
    c  = 1.f + a2*(-0.5f      + a2*((1.f/24.f)  + a2*(-1.f/720.f)));
    sa = 1.f + a2*((-1.f/6.f) + a2*((1.f/120.f) + a2*(-1.f/5040.f)));
    oc = 0.5f + a2*((-1.f/24.f) + a2*(1.f/720.f));
}
__device__ __forceinline__ float j1c(float a2) {
    return (1.f/6.f) + a2*((-1.f/120.f) + a2*(1.f/5040.f));
}
__device__ __forceinline__ void mm3(const float* A, const float* B, float* C) {
#pragma unroll
    for (int p = 0; p < 3; ++p)
#pragma unroll
        for (int q = 0; q < 3; ++q)
            C[p*3+q] = A[p*3+0]*B[0*3+q] + A[p*3+1]*B[1*3+q] + A[p*3+2]*B[2*3+q];
}
__device__ __forceinline__ void normrot(float* X) {
    for (int it = 0; it < 8; ++it) {
        float Y[9], Z[9];
#pragma unroll
        for (int p = 0; p < 3; ++p)
#pragma unroll
            for (int q = 0; q < 3; ++q)
                Y[p*3+q] = X[p*3+0]*X[q*3+0] + X[p*3+1]*X[q*3+1] + X[p*3+2]*X[q*3+2];
        mm3(Y, X, Z);
#pragma unroll
        for (int m = 0; m < 9; ++m) X[m] = 1.5f*X[m] - 0.5f*Z[m];
    }
}

__global__ void __launch_bounds__(NT, 1)
iekf_kernel(const float* __restrict__ t, const float* __restrict__ u,
            const float* __restrict__ mc, const float* __restrict__ vmes,
            const float* __restrict__ ang0, float* __restrict__ out, int N)
{
    __shared__ SM s;
    const int tid = threadIdx.x;
    const bool isMat = (tid < 96);
    const int ln = tid - 96;

    // ---------- matrix decodes: 5 slots/thread over 96 threads ----------
    bool eV[5]; int eII[5], eJJ[5], eJJT[5], eIIB[5], eJJ12[5];
    int eAm[5], eAr[5], eBrx[5]; float eAsc[5], eAqv[5]; bool eT9f[5];
#pragma unroll
    for (int sl = 0; sl < 5; ++sl) {
        int e = tid + sl*96;
        eV[sl] = isMat && (e < 441);
        int ii = 0, jj = 0;
        if (eV[sl]) { ii = e/21; jj = e - ii*21; }
        eII[sl]=ii; eJJ[sl]=jj; eJJT[sl]=jj*21+ii; eIIB[sl]=ii*21; eJJ12[sl]=jj*12;
        eT9f[sl] = (ii < 9);
        int am = 2, ar = 0, brx = 0; float asc = 0.f, aqv = 0.f;
        if (ii<3 && jj<3)                      { am=0; ar=ii*3;     brx=jj*3;     asc=0.001f; }
        else if (ii>=3&&ii<6&&jj>=3&&jj<6)     { am=0; ar=(ii-3)*3; brx=(jj-3)*3; asc=0.01f;  }
        else if (ii==jj) { am=1; aqv=(ii>=9&&ii<12)?6e-9f:(ii>=12&&ii<15)?2e-4f:(ii>=15)?1e-9f:0.f; }
        eAm[sl]=am; eAr[sl]=ar; eBrx[sl]=brx; eAsc[sl]=asc; eAqv[sl]=aqv;
    }
    // T9 slots
    const int t9aR12 = (tid/21)*12, t9aC = tid - (tid/21)*21;
    const int t9k2 = tid + 96; const bool t9bV = isMat && (t9k2 < 189);
    int t9bR12 = 0, t9bC = 0;
    if (t9bV) { int r = t9k2/21; t9bR12 = r*12; t9bC = t9k2 - r*21; }
    // L decodes
    int Lbrr = 0, Lrr = 0, Lbc = 0, Lj = 0;
    if (isMat) {
        int r = tid/12, cc = tid - r*12;
        Lbrr = r/3; Lrr = r - Lbrr*3; Lbc = cc/3; Lj = cc - Lbc*3;
    }
    const bool l2V = isMat && (tid < 12);
    const int L2bc = tid/3, L2j = tid - L2bc*3;
    // out pointers (tid<33)
    float* outP = out; int outStride = 0;
    if (tid < 9)       { outP = out + tid;              outStride = 9; }
    else if (tid < 12) { outP = out + 9*N  + (tid-9);   outStride = 3; }
    else if (tid < 15) { outP = out + 12*N + (tid-12);  outStride = 3; }
    else if (tid < 18) { outP = out + 15*N + (tid-15);  outStride = 3; }
    else if (tid < 21) { outP = out + 18*N + (tid-18);  outStride = 3; }
    else if (tid < 30) { outP = out + 21*N + (tid-21);  outStride = 9; }
    else if (tid < 33) { outP = out + 30*N + (tid-30);  outStride = 3; }
    // prefetch pointers (tid 64..72)
    const float* pfP = t; int pfStride = 0;
    const bool pfV = (tid >= 64 && tid < 73);
    if (pfV) {
        int q = tid - 64;
        if (q == 0)      { pfP = t  + 2;           pfStride = 1; }
        else if (q < 7)  { pfP = u  + 12 + (q-1);  pfStride = 6; }
        else             { pfP = mc + 4  + (q-7);  pfStride = 2; }
    }

    // lane-0 persistent state; lane-1 owns Rci
    float Rg[9], Vg[3], Ppg[3], Bomg[3], Bacg[3], Tcig[3];
    float rn[9], vn[3], pn3[3];
    float RcigL[9];   // valid on lane 1 (tid 97)

    // ---------- prologue ----------
    float tprev = t[0];
#pragma unroll
    for (int sl = 0; sl < 5; ++sl) if (eV[sl]) {
        int e = tid + sl*96;
        int ii = eII[sl], jj = eJJ[sl];
        float pv = 0.f;
        if (ii == jj) {
            if (ii < 2) pv = 0.001f;
            else if (ii >= 3 && ii < 5) pv = 0.1f;
            else if (ii >= 9 && ii < 12) pv = 0.006f;
            else if (ii >= 12 && ii < 15) pv = 0.004f;
            else if (ii >= 15 && ii < 18) pv = 1e-6f;
            else if (ii >= 18) pv = 0.005f;
        }
        s.Pn[e] = pv;
    }
    if (tid < 42) s.HP[tid] = 0.f;
    if (tid == 42) { s.S3[0] = 1.f; s.S3[1] = 0.f; s.S3[2] = 1.f; }
    if (tid < 9) {
        float v;
        if (tid == 0) v = t[1];
        else if (tid < 7) v = u[6 + (tid-1)];
        else v = mc[2 + (tid-7)];
        s.in[1][tid] = v;
    }
    if (tid == 96) {
        float a0 = ang0[0], a1 = ang0[1], a2 = ang0[2];
        float cr = cosf(a0), sr = sinf(a0), cp = cosf(a1), sp = sinf(a1);
        float cy = cosf(a2), sy = sinf(a2);
        float Rx[9] = {1,0,0, 0,cr,-sr, 0,sr,cr};
        float Ry[9] = {cp,0,sp, 0,1,0, -sp,0,cp};
        float Rz[9] = {cy,-sy,0, sy,cy,0, 0,0,1};
        float T[9];
        mm3(Rz, Ry, T); mm3(T, Rx, Rg);
#pragma unroll
        for (int q = 0; q < 3; ++q) {
            Vg[q] = vmes[q]; Ppg[q] = 0.f; Bomg[q] = 0.f; Bacg[q] = 0.f; Tcig[q] = 0.f;
        }
#pragma unroll
        for (int m = 0; m < 9; ++m) s.mir[m] = Rg[m];
#pragma unroll
        for (int q = 0; q < 3; ++q) {
            s.mir[9+q] = Vg[q]; s.mir[12+q] = Ppg[q]; s.mir[15+q] = Bomg[q];
            s.mir[18+q] = Bacg[q]; s.mir[30+q] = Tcig[q];
        }
    }
    if (tid == 97) {
#pragma unroll
        for (int m = 0; m < 9; ++m) {
            RcigL[m] = (m==0||m==4||m==8) ? 1.f : 0.f;
            s.mir[21+m] = RcigL[m];
        }
    }
    __syncthreads();

    // ---------- main loop ----------
    for (int i = 1; i < N; ++i) {
        const int cur = i & 1;
        const float tcv = s.in[cur][0];
        const float dt = tcv - tprev; tprev = tcv;
        const float dt2 = dt*dt;

        // ======== PHASE 1: mat {A=Joseph+gq, L, out, pf-LDG} ; w3 {meas chain} ========
        float pf = 0.f;
        if (isMat) {
            const float dt3 = dt2*dt;
            const float S00 = s.S3[0], S01 = s.S3[1], S11 = s.S3[2];
            const float idet = 1.f / (S00*S11 - S01*S01);
            const float Si00 = S11*idet, Si01 = -S01*idet, Si11 = S00*idet;
#pragma unroll
            for (int sl = 0; sl < 5; ++sl) if (eV[sl]) {
                int e = tid + sl*96;
                float hp0i = s.HP[eII[sl]], hp1i = s.HP[21+eII[sl]];
                float hp0j = s.HP[eJJ[sl]], hp1j = s.HP[21+eJJ[sl]];
                float Ki0 = Si00*hp0i + Si01*hp1i, Ki1 = Si01*hp0i + Si11*hp1i;
                float Kj0 = Si00*hp0j + Si01*hp1j, Kj1 = Si01*hp0j + Si11*hp1j;
                float KSi0 = Ki0*S00 + Ki1*S01, KSi1 = Ki0*S01 + Ki1*S11;
                float pj = 0.5f*(s.Pn[e] + s.Pn[eJJT[sl]])
                         - (Ki0*hp0j + Ki1*hp1j) - (Kj0*hp0i + Kj1*hp1i)
                         + (KSi0*Kj0 + KSi1*Kj1);
                float gq = 0.f;
                if (eAm[sl] == 0) {
                    float d = s.mir[eAr[sl]]*s.mir[eBrx[sl]] + s.mir[eAr[sl]+1]*s.mir[eBrx[sl]+1]
                            + s.mir[eAr[sl]+2]*s.mir[eBrx[sl]+2];
                    gq = eAsc[sl] * dt2 * d;
                } else if (eAm[sl] == 1) gq = eAqv[sl] * dt2;
                s.A[e] = pj + gq;
            }
            {
                const float* Rm = s.mir; const float* Vm = s.mir + 9; const float* Pm = s.mir + 12;
                float v = 0.f;
                if (Lbrr == 0) {
                    if (Lbc == 2) v = -dt * Rm[Lrr*3+Lj];
                } else if (Lbrr == 1) {
                    if (Lbc == 0)      v = dt * SG(Lrr, Lj);
                    else if (Lbc == 2) v = -dt*skewrowdot(Vm, Rm, Lrr, Lj) - 0.5f*dt2*sgR(Rm, Lrr, Lj);
                    else if (Lbc == 3) v = -dt * Rm[Lrr*3+Lj];
                } else {
                    if (Lbc == 0)      v = 0.5f*dt2*SG(Lrr, Lj);
                    else if (Lbc == 1) v = (Lrr == Lj) ? dt : 0.f;
                    else if (Lbc == 2) v = -dt*skewrowdot(Pm, Rm, Lrr, Lj)
                                           - 0.5f*dt2*skewrowdot(Vm, Rm, Lrr, Lj)
                                           - (dt3*(1.f/6.f))*sgR(Rm, Lrr, Lj);
                    else               v = -0.5f*dt2*Rm[Lrr*3+Lj];
                }
                s.L[tid] = v;
                if (l2V) {
                    float v2 = 0.f;
                    if (L2bc == 0)      v2 = 0.5f*dt2*SG(2, L2j);
                    else if (L2bc == 1) v2 = (2 == L2j) ? dt : 0.f;
                    else if (L2bc == 2) v2 = -dt*skewrowdot(Pm, Rm, 2, L2j)
                                             - 0.5f*dt2*skewrowdot(Vm, Rm, 2, L2j)
                                             - (dt3*(1.f/6.f))*sgR(Rm, 2, L2j);
                    else                v2 = -0.5f*dt2*Rm[6+L2j];
                    s.L[96+tid] = v2;
                }
            }
            if (tid < 33) { *outP = s.mir[tid]; outP += outStride; }
            if (pfV && (i + 1 < N)) { pf = *pfP; pfP += pfStride; }
        } else {
            // ---- stage 1 (lane 0): omg, rn, vn, pn3, vig ----
            if (ln == 0) {
                const float gy0 = s.in[cur][1], gy1 = s.in[cur][2], gy2 = s.in[cur][3];
                const float ac0 = s.in[cur][4], ac1 = s.in[cur][5], ac2 = s.in[cur][6];
                float om0 = gy0 - Bomg[0], om1 = gy1 - Bomg[1], om2 = gy2 - Bomg[2];
                s.Om3[0] = om0; s.Om3[1] = om1; s.Om3[2] = om2;
                float phi[3] = {om0*dt, om1*dt, om2*dt};
                float a2 = phi[0]*phi[0] + phi[1]*phi[1] + phi[2]*phi[2];
                float c, sa, oc; so3c(a2, c, sa, oc);
                float E[9];
#pragma unroll
                for (int p = 0; p < 3; ++p)
#pragma unroll
                    for (int q = 0; q < 3; ++q)
                        E[p*3+q] = ((p==q)?c:0.f) + oc*phi[p]*phi[q] + sa*skf(phi, p, q);
#pragma unroll
                for (int p = 0; p < 3; ++p)
#pragma unroll
                    for (int q = 0; q < 3; ++q) {
                        rn[p*3+q] = Rg[p*3+0]*E[0*3+q] + Rg[p*3+1]*E[1*3+q] + Rg[p*3+2]*E[2*3+q];
                        s.Rotn[p*3+q] = rn[p*3+q];
                    }
                float d0 = ac0 - Bacg[0], d1 = ac1 - Bacg[1], d2 = ac2 - Bacg[2];
                float acc[3];
#pragma unroll
                for (int q = 0; q < 3; ++q)
                    acc[q] = Rg[q*3+0]*d0 + Rg[q*3+1]*d1 + Rg[q*3+2]*d2 + ((q==2)?GZ:0.f);
#pragma unroll
                for (int q = 0; q < 3; ++q) {
                    vn[q]  = Vg[q] + acc[q]*dt;
                    pn3[q] = Ppg[q] + Vg[q]*dt + 0.5f*acc[q]*dt2;
                }
#pragma unroll
                for (int q = 0; q < 3; ++q)
                    s.vi3[q] = rn[0*3+q]*vn[0] + rn[1*3+q]*vn[1] + rn[2*3+q]*vn[2];
            }
            __syncwarp();
            // ---- stage 2 (lanes 0,1): h/g row a, r2[a] ----
            if (ln < 2) {
                const int a = ln;
                const float* Rm  = s.mir;
                const float* Vm  = s.mir + 9;
                const float* Rc  = s.mir + 21;
                const float* Tc  = s.mir + 30;
                const float* rns = s.Rotn;
                const float* vis = s.vi3;
                const float* oms = s.Om3;
                float h[12];
#pragma unroll
                for (int j = 0; j < 3; ++j) {
                    h[j]     = rns[j*3+0]*Rc[a+1] + rns[j*3+1]*Rc[3+a+1] + rns[j*3+2]*Rc[6+a+1];
                    h[3+j]   = skf(Tc, a+1, j);
                    h[6+j]   = Rc[a+1]*skf(vis,0,j) + Rc[3+a+1]*skf(vis,1,j) + Rc[6+a+1]*skf(vis,2,j);
                    h[9+j]   = -skf(oms, a+1, j);
                }
                float Lv[9];
#pragma unroll
                for (int rr = 0; rr < 3; ++rr)
#pragma unroll
                    for (int j = 0; j < 3; ++j)
                        Lv[rr*3+j] = -dt*skewrowdot(Vm, Rm, rr, j) - 0.5f*dt2*sgR(Rm, rr, j);
                float g[18];
                g[0] =  h[1]*(dt*GZ);
                g[1] = -h[0]*(dt*GZ);
                g[2] = 0.f;
#pragma unroll
                for (int j = 0; j < 3; ++j) g[3+j] = h[j];
#pragma unroll
                for (int j = 0; j < 3; ++j)
                    g[6+j] = h[3+j] + h[0]*Lv[j] + h[1]*Lv[3+j] + h[2]*Lv[6+j];
#pragma unroll
                for (int j = 0; j < 3; ++j)
                    g[9+j] = -dt*(h[0]*Rm[j] + h[1]*Rm[3+j] + h[2]*Rm[6+j]);
#pragma unroll
                for (int m = 12; m < 18; ++m) g[m] = h[m-6];
#pragma unroll
                for (int m = 0; m < 18; ++m) s.G[a*18+m] = g[m];
                float cxa = (a==0) ? (Tc[2]*oms[0] - Tc[0]*oms[2])
                                   : (Tc[0]*oms[1] - Tc[1]*oms[0]);
                s.r2s[a] = -(Rc[a+1]*vis[0] + Rc[3+a+1]*vis[1] + Rc[6+a+1]*vis[2] + cxa);
            }
        }
        __syncthreads();

        // ======== PHASE 2 (overlapped): mat {T9 -> bar96 -> Pn, pf-STS} ; w3 {GA -> HP,S -> dx -> state} ========
        if (isMat) {
            float a = s.A[tid];
#pragma unroll
            for (int m = 0; m < 12; ++m) {
                int col = (m < 6) ? m : m + 3;
                a += s.L[t9aR12+m] * s.A[col*21 + t9aC];
            }
            s.T9[tid] = a;
            if (t9bV) {
                float b = s.A[t9k2];
#pragma unroll
                for (int m = 0; m < 12; ++m) {
                    int col = (m < 6) ? m : m + 3;
                    b += s.L[t9bR12+m] * s.A[col*21 + t9bC];
                }
                s.T9[t9k2] = b;
            }
            asm volatile("bar.sync 1, 96;" ::: "memory");
#pragma unroll
            for (int sl = 0; sl < 5; ++sl) if (eV[sl]) {
                int e = tid + sl*96;
                float b = eT9f[sl] ? s.T9[e] : s.A[e];
                if (eJJ[sl] < 9) {
#pragma unroll
                    for (int m = 0; m < 12; ++m) {
                        int col = (m < 6) ? m : m + 3;
                        float brc = eT9f[sl] ? s.T9[eIIB[sl]+col] : s.A[eIIB[sl]+col];
                        b += brc * s.L[eJJ12[sl]+m];
                    }
                }
                s.Pn[e] = b;
            }
            if (pfV && (i + 1 < N)) s.in[cur^1][tid-64] = pf;
        } else {
            // ---- GA ----
            if (ln < 21) {
                float a0 = 0.f, a1 = 0.f;
#pragma unroll
                for (int m = 0; m < 18; ++m) {
                    int col = (m < 6) ? m : m + 3;
                    float av = s.A[col*21 + ln];
                    a0 += s.G[m]      * av;
                    a1 += s.G[18+m]   * av;
                }
                s.GA[ln] = a0; s.GA[21+ln] = a1;
            }
            __syncwarp();
            // ---- HP, S ----
            if (ln < 21) {
                float hp0 = s.GA[ln], hp1 = s.GA[21+ln];
                if (ln < 9) {
#pragma unroll
                    for (int m = 0; m < 12; ++m) {
                        int col = (m < 6) ? m : m + 3;
                        float lv = s.L[ln*12+m];
                        hp0 += s.GA[col]    * lv;
                        hp1 += s.GA[21+col] * lv;
                    }
                }
                s.HP[ln] = hp0; s.HP[21+ln] = hp1;
            } else if (ln < 24) {
                int m2 = ln - 21;
                int a = (m2 == 2) ? 1 : 0;
                int bb = (m2 == 0) ? 0 : 1;
                float acc = 0.f;
#pragma unroll
                for (int mm = 0; mm < 18; ++mm) {
                    int col = (mm < 6) ? mm : mm + 3;
                    acc += s.GA[a*21+col] * s.G[bb*18+mm];
                }
                if (a == bb) acc += s.in[cur][7+a];
                s.S3[m2] = acc;
            }
            __syncwarp();
            // ---- dx ----
            if (ln < 21) {
                const float S00 = s.S3[0], S01 = s.S3[1], S11 = s.S3[2];
                const float idet = 1.f / (S00*S11 - S01*S01);
                const float r0 = s.r2s[0], r1 = s.r2s[1];
                const float w0 = idet*( S11*r0 - S01*r1);
                const float w1 = idet*(-S01*r0 + S00*r1);
                s.dxs[ln] = s.HP[ln]*w0 + s.HP[21+ln]*w1;
            }
            __syncwarp();
            // ---- state update: lane 0 (SE23 part), lane 1 (Rci part) ----
            if (ln == 0) {
                float dx[18];
#pragma unroll
                for (int c2 = 0; c2 < 15; ++c2) dx[c2] = s.dxs[c2];
                dx[15] = s.dxs[18]; dx[16] = s.dxs[19]; dx[17] = s.dxs[20];
                float a2 = dx[0]*dx[0] + dx[1]*dx[1] + dx[2]*dx[2];
                float c, sa, oc; so3c(a2, c, sa, oc);
                float j1 = j1c(a2);
                float dR[9], J[9];
#pragma unroll
                for (int p = 0; p < 3; ++p)
#pragma unroll
                    for (int q = 0; q < 3; ++q) {
                        dR[p*3+q] = ((p==q)?c:0.f)  + oc*dx[p]*dx[q] + sa*skf(dx, p, q);
                        J[p*3+q]  = ((p==q)?sa:0.f) + j1*dx[p]*dx[q] + oc*skf(dx, p, q);
                    }
                float x0[3], x1[3];
#pragma unroll
                for (int q = 0; q < 3; ++q) {
                    x0[q] = J[q*3+0]*dx[3] + J[q*3+1]*dx[4] + J[q*3+2]*dx[5];
                    x1[q] = J[q*3+0]*dx[6] + J[q*3+1]*dx[7] + J[q*3+2]*dx[8];
                }
                float Ru[9];
#pragma unroll
                for (int p = 0; p < 3; ++p)
#pragma unroll
                    for (int q = 0; q < 3; ++q)
                        Ru[p*3+q] = dR[p*3+0]*rn[0*3+q] + dR[p*3+1]*rn[1*3+q] + dR[p*3+2]*rn[2*3+q];
#pragma unroll
                for (int q = 0; q < 3; ++q) {
                    float vu = dR[q*3+0]*vn[0]  + dR[q*3+1]*vn[1]  + dR[q*3+2]*vn[2]  + x0[q];
                    float pu = dR[q*3+0]*pn3[0] + dR[q*3+1]*pn3[1] + dR[q*3+2]*pn3[2] + x1[q];
                    Vg[q] = vu; Ppg[q] = pu;
                    Bomg[q] += dx[9+q]; Bacg[q] += dx[12+q]; Tcig[q] += dx[15+q];
                }
#pragma unroll
                for (int m = 0; m < 9; ++m) Rg[m] = Ru[m];
                if (i % 100 == 0) normrot(Rg);
#pragma unroll
                for (int m = 0; m < 9; ++m) s.mir[m] = Rg[m];
#pragma unroll
                for (int q = 0; q < 3; ++q) {
                    s.mir[9+q] = Vg[q]; s.mir[12+q] = Ppg[q]; s.mir[15+q] = Bomg[q];
                    s.mir[18+q] = Bacg[q]; s.mir[30+q] = Tcig[q];
                }
            } else if (ln == 1) {
                float y0 = s.dxs[15], y1 = s.dxs[16], y2 = s.dxs[17];
                float b2 = y0*y0 + y1*y1 + y2*y2;
                float cc2, sa2, oc2; so3c(b2, cc2, sa2, oc2);
                float yv[3] = {y0, y1, y2};
                float E2[9];
#pragma unroll
                for (int p = 0; p < 3; ++p)
#pragma unroll
                    for (int q = 0; q < 3; ++q)
                        E2[p*3+q] = ((p==q)?cc2:0.f) + oc2*yv[p]*yv[q] + sa2*skf(yv, p, q);
                float Rc2[9];
#pragma unroll
                for (int p = 0; p < 3; ++p)
#pragma unroll
                    for (int q = 0; q < 3; ++q)
                        Rc2[p*3+q] = E2[p*3+0]*RcigL[0*3+q] + E2[p*3+1]*RcigL[1*3+q] + E2[p*3+2]*RcigL[2*3+q];
#pragma unroll
                for (int m = 0; m < 9; ++m) RcigL[m] = Rc2[m];
                if (i % 1000 == 0) normrot(RcigL);
#pragma unroll
                for (int m = 0; m < 9; ++m) s.mir[21+m] = RcigL[m];
            }
        }
        __syncthreads();
    }

    // ---------- epilogue: final state row ----------
    if (tid < 33) *outP = s.mir[tid];
}

extern "C" void kernel_launch(void* const* d_in, const int* in_sizes, int n_in,
                              void* d_out, int out_size) {
    const float* t    = (const float*)d_in[0];
    const float* u    = (const float*)d_in[1];
    const float* mcov = (const float*)d_in[2];
    const float* vmes = (const float*)d_in[3];
    const float* ang0 = (const float*)d_in[5];
    float* out = (float*)d_out;
    int N = in_sizes[0];
    iekf_kernel<<<1, NT>>>(t, u, mcov, vmes, ang0, out, N);
}